// round 1
// baseline (speedup 1.0000x reference)
#include <cuda_runtime.h>
#include <math.h>

#define B_    4
#define W_    1024
#define BINS_ 1024
#define H_    4
#define DH_   256
#define FF2_  4096
#define FFH_  1024

// ---------------- scratch (static device memory; no allocations) ----------------
__device__ float g_xs [(size_t)B_*W_*BINS_];
__device__ float g_ms [(size_t)B_*W_*BINS_];
__device__ float g_q  [(size_t)B_*W_*BINS_];
__device__ float g_k  [(size_t)B_*W_*BINS_];
__device__ float g_v  [(size_t)B_*W_*BINS_];
__device__ float g_att[(size_t)B_*W_*BINS_];
__device__ float g_hs [(size_t)B_*W_*BINS_];
__device__ float g_hm [(size_t)B_*W_*BINS_];
__device__ float g_t1 [(size_t)B_*W_*BINS_];
__device__ float g_t2 [(size_t)B_*W_*BINS_];
__device__ float g_dwc[(size_t)B_*W_*BINS_];
__device__ float g_ffb[(size_t)B_*W_*FFH_];
__device__ float g_scores[(size_t)B_*H_*W_*W_];
__device__ float g_ffa[(size_t)B_*W_*FF2_];
__device__ float g_dwf[(size_t)B_*W_*FF2_];

// ---------------- input projection: out[b,w,h] = sum_c x[b,c,h,w] * wc[c] ----------------
__global__ void project_kernel(const float* __restrict__ x, const float* __restrict__ wc,
                               int Cn, float* __restrict__ out)
{
    __shared__ float tile[32][33];
    int b  = blockIdx.z;
    int h0 = blockIdx.y * 32, w0 = blockIdx.x * 32;
    int tx = threadIdx.x, ty = threadIdx.y;   // 32 x 8

    float wreg[8];
    #pragma unroll
    for (int c = 0; c < 8; c++) wreg[c] = (c < Cn) ? wc[c] : 0.f;

    #pragma unroll
    for (int r = 0; r < 4; r++) {
        int h = h0 + ty + r * 8;
        float acc = 0.f;
        #pragma unroll
        for (int c = 0; c < 8; c++)
            acc += x[(((size_t)b * Cn + c) * BINS_ + h) * W_ + (w0 + tx)] * wreg[c];
        tile[ty + r * 8][tx] = acc;
    }
    __syncthreads();
    #pragma unroll
    for (int r = 0; r < 4; r++) {
        int w = w0 + ty + r * 8;
        out[((size_t)b * W_ + w) * BINS_ + (h0 + tx)] = tile[tx][ty + r * 8];
    }
}

// ---------------- final transpose: out[b,h,w] = in[b,w,h] ----------------
__global__ void transpose_out_kernel(const float* __restrict__ in, float* __restrict__ out)
{
    __shared__ float tile[32][33];
    int b  = blockIdx.z;
    int w0 = blockIdx.x * 32, h0 = blockIdx.y * 32;
    int tx = threadIdx.x, ty = threadIdx.y;

    #pragma unroll
    for (int r = 0; r < 4; r++)
        tile[ty + r * 8][tx] = in[((size_t)b * W_ + (w0 + ty + r * 8)) * BINS_ + (h0 + tx)];
    __syncthreads();
    #pragma unroll
    for (int r = 0; r < 4; r++)
        out[((size_t)b * BINS_ + (h0 + ty + r * 8)) * W_ + (w0 + tx)] = tile[tx][ty + r * 8];
}

// ---------------- generic SGEMM ----------------
// C[m,n] = sum_k A[m,k] * B'[.,.] (+bias) (act)
//   BT=1: B is [N,K] row-major (NT form);  BT=0: B is [K,N] row-major (NN form)
// batch offsets: off(z) = (z/zdiv)*so + (z%zdiv)*si per operand.
// Requires M%128==0, N%128==0, K%16==0.
__global__ void sgemm_kernel(const float* __restrict__ A, int lda, long soA, long siA,
                             const float* __restrict__ Bp, int ldb, long soB, long siB,
                             const float* __restrict__ bias,
                             float* __restrict__ C, int ldc, long soC, long siC,
                             int K, int zdiv, int BT, int act)
{
    __shared__ float As[16][128];
    __shared__ float Bs[16][128];

    int z = blockIdx.z;
    long zo = z / zdiv, zi = z % zdiv;
    A  += zo * soA + zi * siA;
    Bp += zo * soB + zi * siB;
    C  += zo * soC + zi * siC;

    int m0 = blockIdx.y * 128, n0 = blockIdx.x * 128;
    int tid = threadIdx.x;
    int ty = tid >> 4, tx = tid & 15;

    float acc[8][8];
    #pragma unroll
    for (int i = 0; i < 8; i++)
        #pragma unroll
        for (int j = 0; j < 8; j++) acc[i][j] = 0.f;

    for (int k0 = 0; k0 < K; k0 += 16) {
        #pragma unroll
        for (int l = 0; l < 2; l++) {
            int f = tid + l * 256;
            int r = f >> 2, kk = (f & 3) << 2;
            float4 v = *reinterpret_cast<const float4*>(A + (size_t)(m0 + r) * lda + (k0 + kk));
            As[kk + 0][r] = v.x; As[kk + 1][r] = v.y; As[kk + 2][r] = v.z; As[kk + 3][r] = v.w;
        }
        if (BT) {
            #pragma unroll
            for (int l = 0; l < 2; l++) {
                int f = tid + l * 256;
                int r = f >> 2, kk = (f & 3) << 2;
                float4 v = *reinterpret_cast<const float4*>(Bp + (size_t)(n0 + r) * ldb + (k0 + kk));
                Bs[kk + 0][r] = v.x; Bs[kk + 1][r] = v.y; Bs[kk + 2][r] = v.z; Bs[kk + 3][r] = v.w;
            }
        } else {
            #pragma unroll
            for (int l = 0; l < 2; l++) {
                int f = tid + l * 256;
                int kk = f >> 5, nn = (f & 31) << 2;
                *reinterpret_cast<float4*>(&Bs[kk][nn]) =
                    *reinterpret_cast<const float4*>(Bp + (size_t)(k0 + kk) * ldb + (n0 + nn));
            }
        }
        __syncthreads();
        #pragma unroll
        for (int k = 0; k < 16; k++) {
            float a[8], bv[8];
            *reinterpret_cast<float4*>(&a[0])  = *reinterpret_cast<float4*>(&As[k][ty * 4]);
            *reinterpret_cast<float4*>(&a[4])  = *reinterpret_cast<float4*>(&As[k][64 + ty * 4]);
            *reinterpret_cast<float4*>(&bv[0]) = *reinterpret_cast<float4*>(&Bs[k][tx * 4]);
            *reinterpret_cast<float4*>(&bv[4]) = *reinterpret_cast<float4*>(&Bs[k][64 + tx * 4]);
            #pragma unroll
            for (int i = 0; i < 8; i++)
                #pragma unroll
                for (int j = 0; j < 8; j++)
                    acc[i][j] = fmaf(a[i], bv[j], acc[i][j]);
        }
        __syncthreads();
    }

    #pragma unroll
    for (int i = 0; i < 8; i++) {
        int m = m0 + ((i < 4) ? (ty * 4 + i) : (64 + ty * 4 + (i - 4)));
        #pragma unroll
        for (int jg = 0; jg < 2; jg++) {
            int n = n0 + jg * 64 + tx * 4;
            float4 v;
            float* vv = reinterpret_cast<float*>(&v);
            #pragma unroll
            for (int j = 0; j < 4; j++) {
                float val = acc[i][jg * 4 + j];
                if (bias) val += bias[n + j];
                if (act == 1)      val = (val >= 0.f) ? val : 0.01f * val;
                else if (act == 2) val = val / (1.f + __expf(-val));
                vv[j] = val;
            }
            *reinterpret_cast<float4*>(C + (size_t)m * ldc + n) = v;
        }
    }
}

// ---------------- fused attention scores: s[i,j] = (Q_i.K_j + Q_j.er[:,i]) / 32 ----------------
__global__ void scores_kernel(const float* __restrict__ q, const float* __restrict__ kx,
                              const float* __restrict__ er, float* __restrict__ s)
{
    __shared__ float Qi[16][64], Kj[16][64], Qj[16][64], Er[16][64];
    int bh = blockIdx.z;
    int b = bh >> 2, h = bh & 3;
    const float* qb = q  + ((size_t)b * W_) * BINS_ + h * DH_;
    const float* kb = kx + ((size_t)b * W_) * BINS_ + h * DH_;
    float* sb = s + (size_t)bh * W_ * W_;

    int i0 = blockIdx.y * 64, j0 = blockIdx.x * 64;
    int tid = threadIdx.x, ty = tid >> 4, tx = tid & 15;

    float acc1[4][4] = {}, acc2[4][4] = {};

    for (int k0 = 0; k0 < DH_; k0 += 16) {
        int r = tid >> 2, kk = (tid & 3) << 2;
        {
            float4 v = *reinterpret_cast<const float4*>(qb + (size_t)(i0 + r) * BINS_ + k0 + kk);
            Qi[kk][r] = v.x; Qi[kk + 1][r] = v.y; Qi[kk + 2][r] = v.z; Qi[kk + 3][r] = v.w;
        }
        {
            float4 v = *reinterpret_cast<const float4*>(kb + (size_t)(j0 + r) * BINS_ + k0 + kk);
            Kj[kk][r] = v.x; Kj[kk + 1][r] = v.y; Kj[kk + 2][r] = v.z; Kj[kk + 3][r] = v.w;
        }
        {
            float4 v = *reinterpret_cast<const float4*>(qb + (size_t)(j0 + r) * BINS_ + k0 + kk);
            Qj[kk][r] = v.x; Qj[kk + 1][r] = v.y; Qj[kk + 2][r] = v.z; Qj[kk + 3][r] = v.w;
        }
        {
            int kk2 = tid >> 4, nn = (tid & 15) << 2;
            *reinterpret_cast<float4*>(&Er[kk2][nn]) =
                *reinterpret_cast<const float4*>(er + (size_t)(k0 + kk2) * W_ + i0 + nn);
        }
        __syncthreads();
        #pragma unroll
        for (int k = 0; k < 16; k++) {
            float qi[4], kj[4], qj[4], e[4];
            *reinterpret_cast<float4*>(qi) = *reinterpret_cast<float4*>(&Qi[k][ty * 4]);
            *reinterpret_cast<float4*>(kj) = *reinterpret_cast<float4*>(&Kj[k][tx * 4]);
            *reinterpret_cast<float4*>(qj) = *reinterpret_cast<float4*>(&Qj[k][tx * 4]);
            *reinterpret_cast<float4*>(e)  = *reinterpret_cast<float4*>(&Er[k][ty * 4]);
            #pragma unroll
            for (int i = 0; i < 4; i++)
                #pragma unroll
                for (int j = 0; j < 4; j++) {
                    acc1[i][j] = fmaf(qi[i], kj[j], acc1[i][j]);
                    acc2[i][j] = fmaf(qj[j], e[i],  acc2[i][j]);
                }
        }
        __syncthreads();
    }
    #pragma unroll
    for (int i = 0; i < 4; i++) {
        float4 v;
        float* vv = reinterpret_cast<float*>(&v);
        #pragma unroll
        for (int j = 0; j < 4; j++) vv[j] = (acc1[i][j] + acc2[i][j]) * 0.03125f;
        *reinterpret_cast<float4*>(sb + (size_t)(i0 + ty * 4 + i) * W_ + j0 + tx * 4) = v;
    }
}

// ---------------- row softmax over n=1024 ----------------
__global__ void softmax_kernel(float* __restrict__ s)
{
    const int n = W_;
    float* row = s + (size_t)blockIdx.x * n;
    int tid = threadIdx.x;
    __shared__ float red[8];

    float m = -3.4e38f;
    for (int i = tid; i < n; i += 256) m = fmaxf(m, row[i]);
    #pragma unroll
    for (int o = 16; o; o >>= 1) m = fmaxf(m, __shfl_xor_sync(0xffffffffu, m, o));
    if ((tid & 31) == 0) red[tid >> 5] = m;
    __syncthreads();
    m = red[0];
    #pragma unroll
    for (int wi = 1; wi < 8; wi++) m = fmaxf(m, red[wi]);

    float sum = 0.f;
    for (int i = tid; i < n; i += 256) { float e = __expf(row[i] - m); row[i] = e; sum += e; }
    #pragma unroll
    for (int o = 16; o; o >>= 1) sum += __shfl_xor_sync(0xffffffffu, sum, o);
    __syncthreads();
    if ((tid & 31) == 0) red[tid >> 5] = sum;
    __syncthreads();
    float tot = 0.f;
    #pragma unroll
    for (int wi = 0; wi < 8; wi++) tot += red[wi];
    float inv = 1.f / tot;
    for (int i = tid; i < n; i += 256) row[i] *= inv;
}

// ---------------- fused (a*omega + b + c) -> LayerNorm ----------------
__global__ void ln_kernel(const float* __restrict__ a, const float* __restrict__ bsrc,
                          const float* __restrict__ csrc, const float* __restrict__ omega,
                          const float* __restrict__ g, const float* __restrict__ bet,
                          float* __restrict__ out, int R)
{
    extern __shared__ float sm[];
    __shared__ float rs[8], rq[8];
    size_t base = (size_t)blockIdx.x * R;
    int tid = threadIdx.x;

    float s = 0.f, sq = 0.f;
    for (int i = tid; i < R; i += 256) {
        float v = a[base + i];
        if (omega) v *= omega[i];
        if (bsrc)  v += bsrc[base + i];
        if (csrc)  v += csrc[base + i];
        sm[i] = v; s += v; sq += v * v;
    }
    #pragma unroll
    for (int o = 16; o; o >>= 1) {
        s  += __shfl_xor_sync(0xffffffffu, s, o);
        sq += __shfl_xor_sync(0xffffffffu, sq, o);
    }
    if ((tid & 31) == 0) { rs[tid >> 5] = s; rq[tid >> 5] = sq; }
    __syncthreads();
    float ts = 0.f, tq = 0.f;
    #pragma unroll
    for (int wi = 0; wi < 8; wi++) { ts += rs[wi]; tq += rq[wi]; }
    float mean = ts / (float)R;
    float var  = tq / (float)R - mean * mean;
    float inv  = rsqrtf(var + 1e-5f);
    for (int i = tid; i < R; i += 256)
        out[base + i] = (sm[i] - mean) * inv * g[i] + bet[i];
}

// ---------------- depthwise conv along w, layout [B, W, Ch] ----------------
__global__ void dwconv_kernel(const float* __restrict__ in, const float* __restrict__ wk,
                              float* __restrict__ out, int Ch, int Kt, int pad)
{
    int c = blockIdx.x * blockDim.x + threadIdx.x;
    int w = blockIdx.y, b = blockIdx.z;
    const float* ib = in + ((size_t)b * W_) * Ch;
    float acc = 0.f;
    for (int t = 0; t < Kt; t++) {
        int ww = w + t - pad;
        if (ww >= 0 && ww < W_) acc += ib[(size_t)ww * Ch + c] * wk[c * Kt + t];
    }
    out[((size_t)b * W_ + w) * Ch + c] = acc;
}

// ---------------- hL[:, :FFH] += hR ----------------
__global__ void add_pad_kernel(float* __restrict__ ffa, const float* __restrict__ ffb)
{
    size_t idx = (size_t)blockIdx.x * 256 + threadIdx.x;   // over B*W*FFH
    size_t row = idx / FFH_, f = idx % FFH_;
    ffa[row * FF2_ + f] += ffb[idx];
}

// =========================================================================
static void launch_sgemm(const float* A, int lda, long soA, long siA,
                         const float* Bp, int ldb, long soB, long siB,
                         const float* bias, float* C, int ldc, long soC, long siC,
                         int M, int N, int K, int nz, int zdiv, int BT, int act)
{
    dim3 g(N / 128, M / 128, nz);
    sgemm_kernel<<<g, 256>>>(A, lda, soA, siA, Bp, ldb, soB, siB, bias,
                             C, ldc, soC, siC, K, zdiv, BT, act);
}

static void run_attn(const float* xin, const float* min_,
                     const float* w, const float* bias, const float* er,
                     float* q, float* k, float* v, float* att, float* scores,
                     float* outp)
{
    const long NK = (long)BINS_ * BINS_;
    const int M = B_ * W_;
    launch_sgemm(xin,  BINS_, 0, 0, w + 0 * NK, BINS_, 0, 0, bias + 0 * BINS_, q,   BINS_, 0, 0, M, BINS_, BINS_, 1, 1, 1, 0);
    launch_sgemm(min_, BINS_, 0, 0, w + 1 * NK, BINS_, 0, 0, bias + 1 * BINS_, k,   BINS_, 0, 0, M, BINS_, BINS_, 1, 1, 1, 0);
    launch_sgemm(min_, BINS_, 0, 0, w + 2 * NK, BINS_, 0, 0, bias + 2 * BINS_, v,   BINS_, 0, 0, M, BINS_, BINS_, 1, 1, 1, 0);

    dim3 gs(W_ / 64, W_ / 64, B_ * H_);
    scores_kernel<<<gs, 256>>>(q, k, er, scores);
    softmax_kernel<<<B_ * H_ * W_, 256>>>(scores);

    // att[b, i, h*DH+d] = sum_j scores[b,h,i,j] * v[b, j, h*DH+d]   (batched NN)
    launch_sgemm(scores, W_, 4L * W_ * W_, (long)W_ * W_,
                 v, BINS_, (long)W_ * BINS_, DH_,
                 nullptr,
                 att, BINS_, (long)W_ * BINS_, DH_,
                 W_, DH_, W_, B_ * H_, H_, 0, 0);

    launch_sgemm(att, BINS_, 0, 0, w + 3 * NK, BINS_, 0, 0, bias + 3 * BINS_, outp, BINS_, 0, 0, M, BINS_, BINS_, 1, 1, 1, 0);
}

extern "C" void kernel_launch(void* const* d_in, const int* in_sizes, int n_in,
                              void* d_out, int out_size)
{
    (void)in_sizes; (void)n_in; (void)out_size;

    const float* x      = (const float*)d_in[0];
    const float* mem    = (const float*)d_in[1];
    const float* in_w   = (const float*)d_in[2];
    const float* skip_w = (const float*)d_in[3];
    const float* attn_w = (const float*)d_in[4];
    const float* attn_b = (const float*)d_in[5];
    const float* er     = (const float*)d_in[6];
    const float* omega  = (const float*)d_in[7];
    const float* ln_g   = (const float*)d_in[8];
    const float* ln_b   = (const float*)d_in[9];
    const float* ln2_g  = (const float*)d_in[10];
    const float* ln2_b  = (const float*)d_in[11];
    const float* c1L_dw = (const float*)d_in[12];
    const float* c1L_pw = (const float*)d_in[13];
    const float* c1R_dw = (const float*)d_in[14];
    const float* c1R_pw = (const float*)d_in[15];
    const float* c2_dw  = (const float*)d_in[16];
    const float* c2_pw  = (const float*)d_in[17];
    const float* c3_w   = (const float*)d_in[18];
    const float* c4_w   = (const float*)d_in[19];

    float *p_xs, *p_ms, *p_q, *p_k, *p_v, *p_att, *p_hs, *p_hm, *p_t1, *p_t2;
    float *p_dwc, *p_ffb, *p_scores, *p_ffa, *p_dwf;
    cudaGetSymbolAddress((void**)&p_xs,  g_xs);
    cudaGetSymbolAddress((void**)&p_ms,  g_ms);
    cudaGetSymbolAddress((void**)&p_q,   g_q);
    cudaGetSymbolAddress((void**)&p_k,   g_k);
    cudaGetSymbolAddress((void**)&p_v,   g_v);
    cudaGetSymbolAddress((void**)&p_att, g_att);
    cudaGetSymbolAddress((void**)&p_hs,  g_hs);
    cudaGetSymbolAddress((void**)&p_hm,  g_hm);
    cudaGetSymbolAddress((void**)&p_t1,  g_t1);
    cudaGetSymbolAddress((void**)&p_t2,  g_t2);
    cudaGetSymbolAddress((void**)&p_dwc, g_dwc);
    cudaGetSymbolAddress((void**)&p_ffb, g_ffb);
    cudaGetSymbolAddress((void**)&p_scores, g_scores);
    cudaGetSymbolAddress((void**)&p_ffa, g_ffa);
    cudaGetSymbolAddress((void**)&p_dwf, g_dwf);

    const int  M  = B_ * W_;
    const long ANK = 4L * BINS_ * BINS_;   // per-attention weight stride
    const long ERS = (long)DH_ * W_;

    // input / skip projections
    {
        dim3 g(W_ / 32, BINS_ / 32, B_), blk(32, 8);
        project_kernel<<<g, blk>>>(x,   in_w,   8, p_xs);
        project_kernel<<<g, blk>>>(mem, skip_w, 8, p_ms);
    }

    // self_attn1 / enc_attn1
    run_attn(p_xs, p_xs, attn_w + 0 * ANK, attn_b + 0 * 4 * BINS_, er + 0 * ERS,
             p_q, p_k, p_v, p_att, p_scores, p_hs);
    run_attn(p_xs, p_ms, attn_w + 1 * ANK, attn_b + 1 * 4 * BINS_, er + 1 * ERS,
             p_q, p_k, p_v, p_att, p_scores, p_hm);

    // x1 = LN(xs*omega0 + hs + hm)
    ln_kernel<<<M, 256, BINS_ * 4>>>(p_xs, p_hs, p_hm, omega + 0 * BINS_,
                                     ln_g + 0 * BINS_, ln_b + 0 * BINS_, p_t1, BINS_);

    // conv block
    dwconv_kernel<<<dim3(BINS_ / 256, W_, B_), 256>>>(p_t1, c1L_dw, p_dwc, BINS_, 11, 5);
    launch_sgemm(p_dwc, BINS_, 0, 0, c1L_pw, BINS_, 0, 0, nullptr, p_ffa, FF2_, 0, 0,
                 M, FF2_, BINS_, 1, 1, 1, 1 /*lrelu*/);
    dwconv_kernel<<<dim3(BINS_ / 256, W_, B_), 256>>>(p_t1, c1R_dw, p_dwc, BINS_, 7, 3);
    launch_sgemm(p_dwc, BINS_, 0, 0, c1R_pw, BINS_, 0, 0, nullptr, p_ffb, FFH_, 0, 0,
                 M, FFH_, BINS_, 1, 1, 1, 0);
    add_pad_kernel<<<(B_ * W_ * FFH_) / 256, 256>>>(p_ffa, p_ffb);
    ln_kernel<<<M, 256, FF2_ * 4>>>(p_ffa, nullptr, nullptr, nullptr, ln2_g, ln2_b, p_ffa, FF2_);
    dwconv_kernel<<<dim3(FF2_ / 256, W_, B_), 256>>>(p_ffa, c2_dw, p_dwf, FF2_, 7, 3);
    launch_sgemm(p_dwf, FF2_, 0, 0, c2_pw, FF2_, 0, 0, nullptr, p_hs, BINS_, 0, 0,
                 M, BINS_, FF2_, 1, 1, 1, 0);

    // x2 = LN(x1*omega1 + h)
    ln_kernel<<<M, 256, BINS_ * 4>>>(p_t1, p_hs, nullptr, omega + 1 * BINS_,
                                     ln_g + 1 * BINS_, ln_b + 1 * BINS_, p_t2, BINS_);

    // self_attn2 ; x3 = LN(x2*omega2 + h)
    run_attn(p_t2, p_t2, attn_w + 2 * ANK, attn_b + 2 * 4 * BINS_, er + 2 * ERS,
             p_q, p_k, p_v, p_att, p_scores, p_hs);
    ln_kernel<<<M, 256, BINS_ * 4>>>(p_t2, p_hs, nullptr, omega + 2 * BINS_,
                                     ln_g + 2 * BINS_, ln_b + 2 * BINS_, p_t1, BINS_);

    // enc_attn2 ; x4 = LN(x3*omega3 + h)
    run_attn(p_t1, p_ms, attn_w + 3 * ANK, attn_b + 3 * 4 * BINS_, er + 3 * ERS,
             p_q, p_k, p_v, p_att, p_scores, p_hs);
    ln_kernel<<<M, 256, BINS_ * 4>>>(p_t1, p_hs, nullptr, omega + 3 * BINS_,
                                     ln_g + 3 * BINS_, ln_b + 3 * BINS_, p_t2, BINS_);

    // FFN: silu(x4 @ c3^T) @ c4^T
    launch_sgemm(p_t2, BINS_, 0, 0, c3_w, BINS_, 0, 0, nullptr, p_ffa, FF2_, 0, 0,
                 M, FF2_, BINS_, 1, 1, 1, 2 /*silu*/);
    launch_sgemm(p_ffa, FF2_, 0, 0, c4_w, FF2_, 0, 0, nullptr, p_hs, BINS_, 0, 0,
                 M, BINS_, FF2_, 1, 1, 1, 0);

    // out = LN(x4*omega4 + h), then transpose to [B, BINS, W]
    ln_kernel<<<M, 256, BINS_ * 4>>>(p_t2, p_hs, nullptr, omega + 4 * BINS_,
                                     ln_g + 4 * BINS_, ln_b + 4 * BINS_, p_t1, BINS_);
    {
        dim3 g(W_ / 32, BINS_ / 32, B_), blk(32, 8);
        transpose_out_kernel<<<g, blk>>>(p_t1, (float*)d_out);
    }
}

// round 2
// speedup vs baseline: 1.9989x; 1.9989x over previous
#include <cuda_runtime.h>
#include <math.h>

#define B_    4
#define W_    1024
#define BINS_ 1024
#define H_    4
#define DH_   256
#define FF2_  4096
#define FFH_  1024

// ---------------- scratch (static device memory; no allocations) ----------------
__device__ float g_xs [(size_t)B_*W_*BINS_];
__device__ float g_ms [(size_t)B_*W_*BINS_];
__device__ float g_q  [(size_t)B_*W_*BINS_];
__device__ float g_k  [(size_t)B_*W_*BINS_];
__device__ float g_v  [(size_t)B_*W_*BINS_];
__device__ float g_att[(size_t)B_*W_*BINS_];
__device__ float g_hs [(size_t)B_*W_*BINS_];
__device__ float g_hm [(size_t)B_*W_*BINS_];
__device__ float g_t1 [(size_t)B_*W_*BINS_];
__device__ float g_t2 [(size_t)B_*W_*BINS_];
__device__ float g_dwc[(size_t)B_*W_*BINS_];
__device__ float g_ffb[(size_t)B_*W_*FFH_];
__device__ float g_scores[(size_t)B_*H_*W_*W_];
__device__ float g_ffa[(size_t)B_*W_*FF2_];
__device__ float g_dwf[(size_t)B_*W_*FF2_];

// ---------------- tf32 helpers ----------------
__device__ __forceinline__ unsigned f2tf(float f) {
    unsigned r;
    asm("cvt.rna.tf32.f32 %0, %1;" : "=r"(r) : "f"(f));
    return r;
}

__device__ __forceinline__ void mma8(float* d, const unsigned* a, const unsigned* b) {
    asm("mma.sync.aligned.m16n8k8.row.col.f32.tf32.tf32.f32 "
        "{%0,%1,%2,%3},{%4,%5,%6,%7},{%8,%9},{%0,%1,%2,%3};"
        : "+f"(d[0]), "+f"(d[1]), "+f"(d[2]), "+f"(d[3])
        : "r"(a[0]), "r"(a[1]), "r"(a[2]), "r"(a[3]), "r"(b[0]), "r"(b[1]));
}

__device__ __forceinline__ float apply_act(float v, int act) {
    if (act == 1) return (v >= 0.f) ? v : 0.01f * v;
    if (act == 2) return v / (1.f + __expf(-v));
    return v;
}

// ---------------- input projection: out[b,w,h] = sum_c x[b,c,h,w] * wc[c] ----------------
__global__ void project_kernel(const float* __restrict__ x, const float* __restrict__ wc,
                               int Cn, float* __restrict__ out)
{
    __shared__ float tile[32][33];
    int b  = blockIdx.z;
    int h0 = blockIdx.y * 32, w0 = blockIdx.x * 32;
    int tx = threadIdx.x, ty = threadIdx.y;   // 32 x 8

    float wreg[8];
    #pragma unroll
    for (int c = 0; c < 8; c++) wreg[c] = (c < Cn) ? wc[c] : 0.f;

    #pragma unroll
    for (int r = 0; r < 4; r++) {
        int h = h0 + ty + r * 8;
        float acc = 0.f;
        #pragma unroll
        for (int c = 0; c < 8; c++)
            acc += x[(((size_t)b * Cn + c) * BINS_ + h) * W_ + (w0 + tx)] * wreg[c];
        tile[ty + r * 8][tx] = acc;
    }
    __syncthreads();
    #pragma unroll
    for (int r = 0; r < 4; r++) {
        int w = w0 + ty + r * 8;
        out[((size_t)b * W_ + w) * BINS_ + (h0 + tx)] = tile[tx][ty + r * 8];
    }
}

// ---------------- final transpose: out[b,h,w] = in[b,w,h] ----------------
__global__ void transpose_out_kernel(const float* __restrict__ in, float* __restrict__ out)
{
    __shared__ float tile[32][33];
    int b  = blockIdx.z;
    int w0 = blockIdx.x * 32, h0 = blockIdx.y * 32;
    int tx = threadIdx.x, ty = threadIdx.y;

    #pragma unroll
    for (int r = 0; r < 4; r++)
        tile[ty + r * 8][tx] = in[((size_t)b * W_ + (w0 + ty + r * 8)) * BINS_ + (h0 + tx)];
    __syncthreads();
    #pragma unroll
    for (int r = 0; r < 4; r++)
        out[((size_t)b * BINS_ + (h0 + ty + r * 8)) * W_ + (w0 + tx)] = tile[tx][ty + r * 8];
}

// ---------------- tf32 tensor-core GEMM ----------------
// C[m,n] = sum_k A[m,k] * B'[.,.] (+bias) (act)
//   BT=1: B is [N,K] row-major (NT form);  BT=0: B is [K,N] row-major (NN form)
// batch offsets: off(z) = (z/zdiv)*so + (z%zdiv)*si per operand.
// Requires M%128==0, N%128==0, K%32==0.
template <int BT>
__global__ void __launch_bounds__(256)
tgemm_kernel(const float* __restrict__ A, int lda, long soA, long siA,
             const float* __restrict__ Bp, int ldb, long soB, long siB,
             const float* __restrict__ bias,
             float* __restrict__ C, int ldc, long soC, long siC,
             int K, int zdiv, int act)
{
    __shared__ __align__(16) unsigned As[128][36];
    __shared__ __align__(16) unsigned Bsm[128 * 36];   // BT: [n][36]; NN: [k][132]

    int z = blockIdx.z;
    long zo = z / zdiv, zi = z % zdiv;
    A  += zo * soA + zi * siA;
    Bp += zo * soB + zi * siB;
    C  += zo * soC + zi * siC;

    int m0 = blockIdx.y * 128, n0 = blockIdx.x * 128;
    int tid  = threadIdx.x;
    int lane = tid & 31, wid = tid >> 5;
    int g = lane >> 2, tg = lane & 3;
    int wm = wid & 3, wn = wid >> 2;      // warp grid 4 (m) x 2 (n)

    float acc[2][8][4];
    #pragma unroll
    for (int i = 0; i < 2; i++)
        #pragma unroll
        for (int j = 0; j < 8; j++)
            #pragma unroll
            for (int l = 0; l < 4; l++) acc[i][j][l] = 0.f;

    uint4 pa[4], pb[4];

    // --- load chunk 0 into regs ---
    #pragma unroll
    for (int i = 0; i < 4; i++) {
        int idx = tid + i * 256;
        int r = idx >> 3, c = (idx & 7) << 2;
        float4 v = *reinterpret_cast<const float4*>(A + (size_t)(m0 + r) * lda + c);
        pa[i].x = f2tf(v.x); pa[i].y = f2tf(v.y); pa[i].z = f2tf(v.z); pa[i].w = f2tf(v.w);
        if (BT) {
            float4 w = *reinterpret_cast<const float4*>(Bp + (size_t)(n0 + r) * ldb + c);
            pb[i].x = f2tf(w.x); pb[i].y = f2tf(w.y); pb[i].z = f2tf(w.z); pb[i].w = f2tf(w.w);
        } else {
            int kr = idx >> 5, cn = (idx & 31) << 2;
            float4 w = *reinterpret_cast<const float4*>(Bp + (size_t)kr * ldb + n0 + cn);
            pb[i].x = f2tf(w.x); pb[i].y = f2tf(w.y); pb[i].z = f2tf(w.z); pb[i].w = f2tf(w.w);
        }
    }
    // store chunk 0
    #pragma unroll
    for (int i = 0; i < 4; i++) {
        int idx = tid + i * 256;
        int r = idx >> 3, c = (idx & 7) << 2;
        *reinterpret_cast<uint4*>(&As[r][c]) = pa[i];
        if (BT) {
            *reinterpret_cast<uint4*>(&Bsm[r * 36 + c]) = pb[i];
        } else {
            int kr = idx >> 5, cn = (idx & 31) << 2;
            *reinterpret_cast<uint4*>(&Bsm[kr * 132 + cn]) = pb[i];
        }
    }
    __syncthreads();

    for (int k0 = 0; k0 < K; k0 += 32) {
        bool more = (k0 + 32) < K;
        if (more) {
            #pragma unroll
            for (int i = 0; i < 4; i++) {
                int idx = tid + i * 256;
                int r = idx >> 3, c = (idx & 7) << 2;
                float4 v = *reinterpret_cast<const float4*>(A + (size_t)(m0 + r) * lda + (k0 + 32) + c);
                pa[i].x = f2tf(v.x); pa[i].y = f2tf(v.y); pa[i].z = f2tf(v.z); pa[i].w = f2tf(v.w);
                if (BT) {
                    float4 w = *reinterpret_cast<const float4*>(Bp + (size_t)(n0 + r) * ldb + (k0 + 32) + c);
                    pb[i].x = f2tf(w.x); pb[i].y = f2tf(w.y); pb[i].z = f2tf(w.z); pb[i].w = f2tf(w.w);
                } else {
                    int kr = idx >> 5, cn = (idx & 31) << 2;
                    float4 w = *reinterpret_cast<const float4*>(Bp + (size_t)(k0 + 32 + kr) * ldb + n0 + cn);
                    pb[i].x = f2tf(w.x); pb[i].y = f2tf(w.y); pb[i].z = f2tf(w.z); pb[i].w = f2tf(w.w);
                }
            }
        }

        #pragma unroll
        for (int kk = 0; kk < 32; kk += 8) {
            unsigned af[2][4];
            #pragma unroll
            for (int mt = 0; mt < 2; mt++) {
                int m = wm * 32 + mt * 16 + g;
                af[mt][0] = As[m][kk + tg];
                af[mt][1] = As[m + 8][kk + tg];
                af[mt][2] = As[m][kk + tg + 4];
                af[mt][3] = As[m + 8][kk + tg + 4];
            }
            unsigned bf[8][2];
            #pragma unroll
            for (int nt = 0; nt < 8; nt++) {
                int n = wn * 64 + nt * 8 + g;
                if (BT) {
                    bf[nt][0] = Bsm[n * 36 + kk + tg];
                    bf[nt][1] = Bsm[n * 36 + kk + tg + 4];
                } else {
                    bf[nt][0] = Bsm[(kk + tg) * 132 + n];
                    bf[nt][1] = Bsm[(kk + tg + 4) * 132 + n];
                }
            }
            #pragma unroll
            for (int mt = 0; mt < 2; mt++)
                #pragma unroll
                for (int nt = 0; nt < 8; nt++)
                    mma8(acc[mt][nt], af[mt], bf[nt]);
        }
        __syncthreads();

        if (more) {
            #pragma unroll
            for (int i = 0; i < 4; i++) {
                int idx = tid + i * 256;
                int r = idx >> 3, c = (idx & 7) << 2;
                *reinterpret_cast<uint4*>(&As[r][c]) = pa[i];
                if (BT) {
                    *reinterpret_cast<uint4*>(&Bsm[r * 36 + c]) = pb[i];
                } else {
                    int kr = idx >> 5, cn = (idx & 31) << 2;
                    *reinterpret_cast<uint4*>(&Bsm[kr * 132 + cn]) = pb[i];
                }
            }
            __syncthreads();
        }
    }

    // epilogue
    #pragma unroll
    for (int mt = 0; mt < 2; mt++) {
        int r0 = m0 + wm * 32 + mt * 16 + g;
        #pragma unroll
        for (int nt = 0; nt < 8; nt++) {
            int c = n0 + wn * 64 + nt * 8 + tg * 2;
            float b0 = bias ? bias[c] : 0.f, b1 = bias ? bias[c + 1] : 0.f;
            float2 v0, v1;
            v0.x = apply_act(acc[mt][nt][0] + b0, act);
            v0.y = apply_act(acc[mt][nt][1] + b1, act);
            v1.x = apply_act(acc[mt][nt][2] + b0, act);
            v1.y = apply_act(acc[mt][nt][3] + b1, act);
            *reinterpret_cast<float2*>(C + (size_t)r0 * ldc + c) = v0;
            *reinterpret_cast<float2*>(C + (size_t)(r0 + 8) * ldc + c) = v1;
        }
    }
}

// ---------------- fused attention scores (tensor core):
// s[i,j] = (Q_i.K_j + Q_j.er[:,i]) / 32 ----------------
__global__ void __launch_bounds__(256)
scores_kernel(const float* __restrict__ q, const float* __restrict__ kx,
              const float* __restrict__ er, float* __restrict__ s)
{
    __shared__ __align__(16) unsigned Qi[128][20];
    __shared__ __align__(16) unsigned Kj[128][20];
    __shared__ __align__(16) unsigned Qj[128][20];
    __shared__ __align__(16) unsigned Et[128][20];   // Et[i][k] = er[k][i0+i]

    int bh = blockIdx.z;
    int b = bh >> 2, h = bh & 3;
    const float* qb = q  + (size_t)b * W_ * BINS_ + h * DH_;
    const float* kb = kx + (size_t)b * W_ * BINS_ + h * DH_;
    float* sb = s + (size_t)bh * W_ * W_;

    int i0 = blockIdx.y * 128, j0 = blockIdx.x * 128;
    int tid  = threadIdx.x;
    int lane = tid & 31, wid = tid >> 5;
    int g = lane >> 2, tg = lane & 3;
    int wm = wid & 3, wn = wid >> 2;

    float acc[2][8][4];
    #pragma unroll
    for (int i = 0; i < 2; i++)
        #pragma unroll
        for (int j = 0; j < 8; j++)
            #pragma unroll
            for (int l = 0; l < 4; l++) acc[i][j][l] = 0.f;

    for (int k0 = 0; k0 < DH_; k0 += 16) {
        #pragma unroll
        for (int it = 0; it < 2; it++) {
            int idx = tid + it * 256;
            int r = idx >> 2, c = (idx & 3) << 2;
            float4 v1 = *reinterpret_cast<const float4*>(qb + (size_t)(i0 + r) * BINS_ + k0 + c);
            Qi[r][c] = f2tf(v1.x); Qi[r][c + 1] = f2tf(v1.y); Qi[r][c + 2] = f2tf(v1.z); Qi[r][c + 3] = f2tf(v1.w);
            float4 v2 = *reinterpret_cast<const float4*>(kb + (size_t)(j0 + r) * BINS_ + k0 + c);
            Kj[r][c] = f2tf(v2.x); Kj[r][c + 1] = f2tf(v2.y); Kj[r][c + 2] = f2tf(v2.z); Kj[r][c + 3] = f2tf(v2.w);
            float4 v3 = *reinterpret_cast<const float4*>(qb + (size_t)(j0 + r) * BINS_ + k0 + c);
            Qj[r][c] = f2tf(v3.x); Qj[r][c + 1] = f2tf(v3.y); Qj[r][c + 2] = f2tf(v3.z); Qj[r][c + 3] = f2tf(v3.w);
            // Er transpose: kr = idx&15, c4 = idx>>4
            int kr = idx & 15, c4 = idx >> 4;
            float4 ve = *reinterpret_cast<const float4*>(er + (size_t)(k0 + kr) * W_ + i0 + c4 * 4);
            Et[c4 * 4 + 0][kr] = f2tf(ve.x);
            Et[c4 * 4 + 1][kr] = f2tf(ve.y);
            Et[c4 * 4 + 2][kr] = f2tf(ve.z);
            Et[c4 * 4 + 3][kr] = f2tf(ve.w);
        }
        __syncthreads();

        #pragma unroll
        for (int kk = 0; kk < 16; kk += 8) {
            unsigned a1[2][4], a2[2][4];
            #pragma unroll
            for (int mt = 0; mt < 2; mt++) {
                int m = wm * 32 + mt * 16 + g;
                a1[mt][0] = Qi[m][kk + tg];     a1[mt][1] = Qi[m + 8][kk + tg];
                a1[mt][2] = Qi[m][kk + tg + 4]; a1[mt][3] = Qi[m + 8][kk + tg + 4];
                a2[mt][0] = Et[m][kk + tg];     a2[mt][1] = Et[m + 8][kk + tg];
                a2[mt][2] = Et[m][kk + tg + 4]; a2[mt][3] = Et[m + 8][kk + tg + 4];
            }
            unsigned b1[8][2], b2[8][2];
            #pragma unroll
            for (int nt = 0; nt < 8; nt++) {
                int n = wn * 64 + nt * 8 + g;
                b1[nt][0] = Kj[n][kk + tg]; b1[nt][1] = Kj[n][kk + tg + 4];
                b2[nt][0] = Qj[n][kk + tg]; b2[nt][1] = Qj[n][kk + tg + 4];
            }
            #pragma unroll
            for (int mt = 0; mt < 2; mt++)
                #pragma unroll
                for (int nt = 0; nt < 8; nt++) {
                    mma8(acc[mt][nt], a1[mt], b1[nt]);
                    mma8(acc[mt][nt], a2[mt], b2[nt]);
                }
        }
        __syncthreads();
    }

    #pragma unroll
    for (int mt = 0; mt < 2; mt++) {
        int r0 = i0 + wm * 32 + mt * 16 + g;
        #pragma unroll
        for (int nt = 0; nt < 8; nt++) {
            int c = j0 + wn * 64 + nt * 8 + tg * 2;
            float2 v0, v1;
            v0.x = acc[mt][nt][0] * 0.03125f;
            v0.y = acc[mt][nt][1] * 0.03125f;
            v1.x = acc[mt][nt][2] * 0.03125f;
            v1.y = acc[mt][nt][3] * 0.03125f;
            *reinterpret_cast<float2*>(sb + (size_t)r0 * W_ + c) = v0;
            *reinterpret_cast<float2*>(sb + (size_t)(r0 + 8) * W_ + c) = v1;
        }
    }
}

// ---------------- row softmax over n=1024 ----------------
__global__ void softmax_kernel(float* __restrict__ s)
{
    const int n = W_;
    float* row = s + (size_t)blockIdx.x * n;
    int tid = threadIdx.x;
    __shared__ float red[8];

    float m = -3.4e38f;
    for (int i = tid; i < n; i += 256) m = fmaxf(m, row[i]);
    #pragma unroll
    for (int o = 16; o; o >>= 1) m = fmaxf(m, __shfl_xor_sync(0xffffffffu, m, o));
    if ((tid & 31) == 0) red[tid >> 5] = m;
    __syncthreads();
    m = red[0];
    #pragma unroll
    for (int wi = 1; wi < 8; wi++) m = fmaxf(m, red[wi]);

    float sum = 0.f;
    for (int i = tid; i < n; i += 256) { float e = __expf(row[i] - m); row[i] = e; sum += e; }
    #pragma unroll
    for (int o = 16; o; o >>= 1) sum += __shfl_xor_sync(0xffffffffu, sum, o);
    __syncthreads();
    if ((tid & 31) == 0) red[tid >> 5] = sum;
    __syncthreads();
    float tot = 0.f;
    #pragma unroll
    for (int wi = 0; wi < 8; wi++) tot += red[wi];
    float inv = 1.f / tot;
    for (int i = tid; i < n; i += 256) row[i] *= inv;
}

// ---------------- fused (a*omega + b + c) -> LayerNorm ----------------
__global__ void ln_kernel(const float* __restrict__ a, const float* __restrict__ bsrc,
                          const float* __restrict__ csrc, const float* __restrict__ omega,
                          const float* __restrict__ g, const float* __restrict__ bet,
                          float* __restrict__ out, int R)
{
    extern __shared__ float sm[];
    __shared__ float rs[8], rq[8];
    size_t base = (size_t)blockIdx.x * R;
    int tid = threadIdx.x;

    float s = 0.f, sq = 0.f;
    for (int i = tid; i < R; i += 256) {
        float v = a[base + i];
        if (omega) v *= omega[i];
        if (bsrc)  v += bsrc[base + i];
        if (csrc)  v += csrc[base + i];
        sm[i] = v; s += v; sq += v * v;
    }
    #pragma unroll
    for (int o = 16; o; o >>= 1) {
        s  += __shfl_xor_sync(0xffffffffu, s, o);
        sq += __shfl_xor_sync(0xffffffffu, sq, o);
    }
    if ((tid & 31) == 0) { rs[tid >> 5] = s; rq[tid >> 5] = sq; }
    __syncthreads();
    float ts = 0.f, tq = 0.f;
    #pragma unroll
    for (int wi = 0; wi < 8; wi++) { ts += rs[wi]; tq += rq[wi]; }
    float mean = ts / (float)R;
    float var  = tq / (float)R - mean * mean;
    float inv  = rsqrtf(var + 1e-5f);
    for (int i = tid; i < R; i += 256)
        out[base + i] = (sm[i] - mean) * inv * g[i] + bet[i];
}

// ---------------- depthwise conv along w, layout [B, W, Ch] ----------------
__global__ void dwconv_kernel(const float* __restrict__ in, const float* __restrict__ wk,
                              float* __restrict__ out, int Ch, int Kt, int pad)
{
    int c = blockIdx.x * blockDim.x + threadIdx.x;
    int w = blockIdx.y, b = blockIdx.z;
    const float* ib = in + ((size_t)b * W_) * Ch;
    float acc = 0.f;
    for (int t = 0; t < Kt; t++) {
        int ww = w + t - pad;
        if (ww >= 0 && ww < W_) acc += ib[(size_t)ww * Ch + c] * wk[c * Kt + t];
    }
    out[((size_t)b * W_ + w) * Ch + c] = acc;
}

// ---------------- hL[:, :FFH] += hR ----------------
__global__ void add_pad_kernel(float* __restrict__ ffa, const float* __restrict__ ffb)
{
    size_t idx = (size_t)blockIdx.x * 256 + threadIdx.x;   // over B*W*FFH
    size_t row = idx / FFH_, f = idx % FFH_;
    ffa[row * FF2_ + f] += ffb[idx];
}

// =========================================================================
static void launch_tgemm(const float* A, int lda, long soA, long siA,
                         const float* Bp, int ldb, long soB, long siB,
                         const float* bias, float* C, int ldc, long soC, long siC,
                         int M, int N, int K, int nz, int zdiv, int BT, int act)
{
    dim3 g(N / 128, M / 128, nz);
    if (BT)
        tgemm_kernel<1><<<g, 256>>>(A, lda, soA, siA, Bp, ldb, soB, siB, bias,
                                    C, ldc, soC, siC, K, zdiv, act);
    else
        tgemm_kernel<0><<<g, 256>>>(A, lda, soA, siA, Bp, ldb, soB, siB, bias,
                                    C, ldc, soC, siC, K, zdiv, act);
}

static void run_attn(const float* xin, const float* min_,
                     const float* w, const float* bias, const float* er,
                     float* q, float* k, float* v, float* att, float* scores,
                     float* outp)
{
    const long NK = (long)BINS_ * BINS_;
    const int M = B_ * W_;
    launch_tgemm(xin,  BINS_, 0, 0, w + 0 * NK, BINS_, 0, 0, bias + 0 * BINS_, q,   BINS_, 0, 0, M, BINS_, BINS_, 1, 1, 1, 0);
    launch_tgemm(min_, BINS_, 0, 0, w + 1 * NK, BINS_, 0, 0, bias + 1 * BINS_, k,   BINS_, 0, 0, M, BINS_, BINS_, 1, 1, 1, 0);
    launch_tgemm(min_, BINS_, 0, 0, w + 2 * NK, BINS_, 0, 0, bias + 2 * BINS_, v,   BINS_, 0, 0, M, BINS_, BINS_, 1, 1, 1, 0);

    dim3 gs(W_ / 128, W_ / 128, B_ * H_);
    scores_kernel<<<gs, 256>>>(q, k, er, scores);
    softmax_kernel<<<B_ * H_ * W_, 256>>>(scores);

    // att[b, i, h*DH+d] = sum_j scores[b,h,i,j] * v[b, j, h*DH+d]   (batched NN)
    launch_tgemm(scores, W_, 4L * W_ * W_, (long)W_ * W_,
                 v, BINS_, (long)W_ * BINS_, DH_,
                 nullptr,
                 att, BINS_, (long)W_ * BINS_, DH_,
                 W_, DH_, W_, B_ * H_, H_, 0, 0);

    launch_tgemm(att, BINS_, 0, 0, w + 3 * NK, BINS_, 0, 0, bias + 3 * BINS_, outp, BINS_, 0, 0, M, BINS_, BINS_, 1, 1, 1, 0);
}

extern "C" void kernel_launch(void* const* d_in, const int* in_sizes, int n_in,
                              void* d_out, int out_size)
{
    (void)in_sizes; (void)n_in; (void)out_size;

    const float* x      = (const float*)d_in[0];
    const float* mem    = (const float*)d_in[1];
    const float* in_w   = (const float*)d_in[2];
    const float* skip_w = (const float*)d_in[3];
    const float* attn_w = (const float*)d_in[4];
    const float* attn_b = (const float*)d_in[5];
    const float* er     = (const float*)d_in[6];
    const float* omega  = (const float*)d_in[7];
    const float* ln_g   = (const float*)d_in[8];
    const float* ln_b   = (const float*)d_in[9];
    const float* ln2_g  = (const float*)d_in[10];
    const float* ln2_b  = (const float*)d_in[11];
    const float* c1L_dw = (const float*)d_in[12];
    const float* c1L_pw = (const float*)d_in[13];
    const float* c1R_dw = (const float*)d_in[14];
    const float* c1R_pw = (const float*)d_in[15];
    const float* c2_dw  = (const float*)d_in[16];
    const float* c2_pw  = (const float*)d_in[17];
    const float* c3_w   = (const float*)d_in[18];
    const float* c4_w   = (const float*)d_in[19];

    float *p_xs, *p_ms, *p_q, *p_k, *p_v, *p_att, *p_hs, *p_hm, *p_t1, *p_t2;
    float *p_dwc, *p_ffb, *p_scores, *p_ffa, *p_dwf;
    cudaGetSymbolAddress((void**)&p_xs,  g_xs);
    cudaGetSymbolAddress((void**)&p_ms,  g_ms);
    cudaGetSymbolAddress((void**)&p_q,   g_q);
    cudaGetSymbolAddress((void**)&p_k,   g_k);
    cudaGetSymbolAddress((void**)&p_v,   g_v);
    cudaGetSymbolAddress((void**)&p_att, g_att);
    cudaGetSymbolAddress((void**)&p_hs,  g_hs);
    cudaGetSymbolAddress((void**)&p_hm,  g_hm);
    cudaGetSymbolAddress((void**)&p_t1,  g_t1);
    cudaGetSymbolAddress((void**)&p_t2,  g_t2);
    cudaGetSymbolAddress((void**)&p_dwc, g_dwc);
    cudaGetSymbolAddress((void**)&p_ffb, g_ffb);
    cudaGetSymbolAddress((void**)&p_scores, g_scores);
    cudaGetSymbolAddress((void**)&p_ffa, g_ffa);
    cudaGetSymbolAddress((void**)&p_dwf, g_dwf);

    const int  M  = B_ * W_;
    const long ANK = 4L * BINS_ * BINS_;   // per-attention weight stride
    const long ERS = (long)DH_ * W_;

    // input / skip projections
    {
        dim3 g(W_ / 32, BINS_ / 32, B_), blk(32, 8);
        project_kernel<<<g, blk>>>(x,   in_w,   8, p_xs);
        project_kernel<<<g, blk>>>(mem, skip_w, 8, p_ms);
    }

    // self_attn1 / enc_attn1
    run_attn(p_xs, p_xs, attn_w + 0 * ANK, attn_b + 0 * 4 * BINS_, er + 0 * ERS,
             p_q, p_k, p_v, p_att, p_scores, p_hs);
    run_attn(p_xs, p_ms, attn_w + 1 * ANK, attn_b + 1 * 4 * BINS_, er + 1 * ERS,
             p_q, p_k, p_v, p_att, p_scores, p_hm);

    // x1 = LN(xs*omega0 + hs + hm)
    ln_kernel<<<M, 256, BINS_ * 4>>>(p_xs, p_hs, p_hm, omega + 0 * BINS_,
                                     ln_g + 0 * BINS_, ln_b + 0 * BINS_, p_t1, BINS_);

    // conv block
    dwconv_kernel<<<dim3(BINS_ / 256, W_, B_), 256>>>(p_t1, c1L_dw, p_dwc, BINS_, 11, 5);
    launch_tgemm(p_dwc, BINS_, 0, 0, c1L_pw, BINS_, 0, 0, nullptr, p_ffa, FF2_, 0, 0,
                 M, FF2_, BINS_, 1, 1, 1, 1 /*lrelu*/);
    dwconv_kernel<<<dim3(BINS_ / 256, W_, B_), 256>>>(p_t1, c1R_dw, p_dwc, BINS_, 7, 3);
    launch_tgemm(p_dwc, BINS_, 0, 0, c1R_pw, BINS_, 0, 0, nullptr, p_ffb, FFH_, 0, 0,
                 M, FFH_, BINS_, 1, 1, 1, 0);
    add_pad_kernel<<<(B_ * W_ * FFH_) / 256, 256>>>(p_ffa, p_ffb);
    ln_kernel<<<M, 256, FF2_ * 4>>>(p_ffa, nullptr, nullptr, nullptr, ln2_g, ln2_b, p_ffa, FF2_);
    dwconv_kernel<<<dim3(FF2_ / 256, W_, B_), 256>>>(p_ffa, c2_dw, p_dwf, FF2_, 7, 3);
    launch_tgemm(p_dwf, FF2_, 0, 0, c2_pw, FF2_, 0, 0, nullptr, p_hs, BINS_, 0, 0,
                 M, BINS_, FF2_, 1, 1, 1, 0);

    // x2 = LN(x1*omega1 + h)
    ln_kernel<<<M, 256, BINS_ * 4>>>(p_t1, p_hs, nullptr, omega + 1 * BINS_,
                                     ln_g + 1 * BINS_, ln_b + 1 * BINS_, p_t2, BINS_);

    // self_attn2 ; x3 = LN(x2*omega2 + h)
    run_attn(p_t2, p_t2, attn_w + 2 * ANK, attn_b + 2 * 4 * BINS_, er + 2 * ERS,
             p_q, p_k, p_v, p_att, p_scores, p_hs);
    ln_kernel<<<M, 256, BINS_ * 4>>>(p_t2, p_hs, nullptr, omega + 2 * BINS_,
                                     ln_g + 2 * BINS_, ln_b + 2 * BINS_, p_t1, BINS_);

    // enc_attn2 ; x4 = LN(x3*omega3 + h)
    run_attn(p_t1, p_ms, attn_w + 3 * ANK, attn_b + 3 * 4 * BINS_, er + 3 * ERS,
             p_q, p_k, p_v, p_att, p_scores, p_hs);
    ln_kernel<<<M, 256, BINS_ * 4>>>(p_t1, p_hs, nullptr, omega + 3 * BINS_,
                                     ln_g + 3 * BINS_, ln_b + 3 * BINS_, p_t2, BINS_);

    // FFN: silu(x4 @ c3^T) @ c4^T
    launch_tgemm(p_t2, BINS_, 0, 0, c3_w, BINS_, 0, 0, nullptr, p_ffa, FF2_, 0, 0,
                 M, FF2_, BINS_, 1, 1, 1, 2 /*silu*/);
    launch_tgemm(p_ffa, FF2_, 0, 0, c4_w, FF2_, 0, 0, nullptr, p_hs, BINS_, 0, 0,
                 M, BINS_, FF2_, 1, 1, 1, 0);

    // out = LN(x4*omega4 + h), then transpose to [B, BINS, W]
    ln_kernel<<<M, 256, BINS_ * 4>>>(p_t2, p_hs, nullptr, omega + 4 * BINS_,
                                     ln_g + 4 * BINS_, ln_b + 4 * BINS_, p_t1, BINS_);
    {
        dim3 g(W_ / 32, BINS_ / 32, B_), blk(32, 8);
        transpose_out_kernel<<<g, blk>>>(p_t1, (float*)d_out);
    }
}

// round 4
// speedup vs baseline: 2.8456x; 1.4236x over previous
#include <cuda_runtime.h>
#include <math.h>

#define B_    4
#define W_    1024
#define BINS_ 1024
#define H_    4
#define DH_   256
#define FF2_  4096
#define FFH_  1024

// stage layout for pipelined GEMMs: A(4608 floats) + B(4608 floats) per stage, 2 stages
#define STAGE_F 9216
#define SMEM_BYTES (2 * STAGE_F * 4)

// ---------------- scratch (static device memory; no allocations) ----------------
__device__ float g_xs [(size_t)B_*W_*BINS_];
__device__ float g_ms [(size_t)B_*W_*BINS_];
__device__ float g_q  [(size_t)B_*W_*BINS_];
__device__ float g_k  [(size_t)B_*W_*BINS_];
__device__ float g_v  [(size_t)B_*W_*BINS_];
__device__ float g_att[(size_t)B_*W_*BINS_];
__device__ float g_hs [(size_t)B_*W_*BINS_];
__device__ float g_hm [(size_t)B_*W_*BINS_];
__device__ float g_t1 [(size_t)B_*W_*BINS_];
__device__ float g_t2 [(size_t)B_*W_*BINS_];
__device__ float g_dwc[(size_t)B_*W_*BINS_];
__device__ float g_ffb[(size_t)B_*W_*FFH_];
__device__ float g_scores[(size_t)B_*H_*W_*W_];
__device__ float g_ffa[(size_t)B_*W_*FF2_];
__device__ float g_dwf[(size_t)B_*W_*FF2_];

// ---------------- helpers ----------------
__device__ __forceinline__ unsigned f2tf(float f) {
    unsigned r;
    asm("cvt.rna.tf32.f32 %0, %1;" : "=r"(r) : "f"(f));
    return r;
}

__device__ __forceinline__ void mma8(float* d, const unsigned* a, const unsigned* b) {
    asm("mma.sync.aligned.m16n8k8.row.col.f32.tf32.tf32.f32 "
        "{%0,%1,%2,%3},{%4,%5,%6,%7},{%8,%9},{%0,%1,%2,%3};"
        : "+f"(d[0]), "+f"(d[1]), "+f"(d[2]), "+f"(d[3])
        : "r"(a[0]), "r"(a[1]), "r"(a[2]), "r"(a[3]), "r"(b[0]), "r"(b[1]));
}

__device__ __forceinline__ void cp16(float* smem_dst, const float* gsrc) {
    unsigned d = (unsigned)__cvta_generic_to_shared(smem_dst);
    asm volatile("cp.async.cg.shared.global [%0], [%1], 16;" :: "r"(d), "l"(gsrc));
}
__device__ __forceinline__ void cp_commit() { asm volatile("cp.async.commit_group;"); }
__device__ __forceinline__ void cp_wait1()  { asm volatile("cp.async.wait_group 1;"); }
__device__ __forceinline__ void cp_wait0()  { asm volatile("cp.async.wait_group 0;"); }

__device__ __forceinline__ float apply_act(float v, int act) {
    if (act == 1) return (v >= 0.f) ? v : 0.01f * v;
    if (act == 2) return v / (1.f + __expf(-v));
    return v;
}

// ---------------- input projection: out[b,w,h] = sum_c x[b,c,h,w] * wc[c] ----------------
__global__ void project_kernel(const float* __restrict__ x, const float* __restrict__ wc,
                               int Cn, float* __restrict__ out)
{
    __shared__ float tile[32][33];
    int b  = blockIdx.z;
    int h0 = blockIdx.y * 32, w0 = blockIdx.x * 32;
    int tx = threadIdx.x, ty = threadIdx.y;   // 32 x 8

    float wreg[8];
    #pragma unroll
    for (int c = 0; c < 8; c++) wreg[c] = (c < Cn) ? wc[c] : 0.f;

    #pragma unroll
    for (int r = 0; r < 4; r++) {
        int h = h0 + ty + r * 8;
        float acc = 0.f;
        #pragma unroll
        for (int c = 0; c < 8; c++)
            acc += x[(((size_t)b * Cn + c) * BINS_ + h) * W_ + (w0 + tx)] * wreg[c];
        tile[ty + r * 8][tx] = acc;
    }
    __syncthreads();
    #pragma unroll
    for (int r = 0; r < 4; r++) {
        int w = w0 + ty + r * 8;
        out[((size_t)b * W_ + w) * BINS_ + (h0 + tx)] = tile[tx][ty + r * 8];
    }
}

// ---------------- final transpose: out[b,h,w] = in[b,w,h] ----------------
__global__ void transpose_out_kernel(const float* __restrict__ in, float* __restrict__ out)
{
    __shared__ float tile[32][33];
    int b  = blockIdx.z;
    int w0 = blockIdx.x * 32, h0 = blockIdx.y * 32;
    int tx = threadIdx.x, ty = threadIdx.y;

    #pragma unroll
    for (int r = 0; r < 4; r++)
        tile[ty + r * 8][tx] = in[((size_t)b * W_ + (w0 + ty + r * 8)) * BINS_ + (h0 + tx)];
    __syncthreads();
    #pragma unroll
    for (int r = 0; r < 4; r++)
        out[((size_t)b * BINS_ + (h0 + ty + r * 8)) * W_ + (w0 + tx)] = tile[tx][ty + r * 8];
}

// ---------------- tf32 tensor-core GEMM, cp.async double-buffered ----------------
// BT=1: B is [N,K] row-major (NT); BT=0: B is [K,N] row-major (NN)
// Requires M%128==0, N%128==0, K%32==0.
template <int BT>
__global__ void __launch_bounds__(256, 2)
tgemm_kernel(const float* __restrict__ A, int lda, long soA, long siA,
             const float* __restrict__ Bp, int ldb, long soB, long siB,
             const float* __restrict__ bias,
             float* __restrict__ C, int ldc, long soC, long siC,
             int K, int zdiv, int act)
{
    extern __shared__ float smem[];

    int z = blockIdx.z;
    long zo = z / zdiv, zi = z % zdiv;
    A  += zo * soA + zi * siA;
    Bp += zo * soB + zi * siB;
    C  += zo * soC + zi * siC;

    int m0 = blockIdx.y * 128, n0 = blockIdx.x * 128;
    int tid  = threadIdx.x;
    int lane = tid & 31, wid = tid >> 5;
    int g = lane >> 2, tg = lane & 3;
    int wm = wid & 3, wn = wid >> 2;      // warp grid 4 (m) x 2 (n)

    float acc[2][8][4] = {};

    auto issue = [&](int k0, int s) {
        float* Sa = smem + s * STAGE_F;
        float* Sb = Sa + 4608;
        #pragma unroll
        for (int i = 0; i < 4; i++) {
            int idx = tid + i * 256;
            int r = idx >> 3, c = (idx & 7) << 2;
            cp16(Sa + r * 36 + c, A + (size_t)(m0 + r) * lda + k0 + c);
            if (BT) {
                cp16(Sb + r * 36 + c, Bp + (size_t)(n0 + r) * ldb + k0 + c);
            } else {
                int kr = idx >> 5, cn = (idx & 31) << 2;
                cp16(Sb + kr * 132 + cn, Bp + (size_t)(k0 + kr) * ldb + n0 + cn);
            }
        }
        cp_commit();
    };

    int nc = K >> 5;
    issue(0, 0);
    for (int ch = 0; ch < nc; ch++) {
        if (ch + 1 < nc) { issue((ch + 1) << 5, (ch + 1) & 1); cp_wait1(); }
        else             { cp_wait0(); }
        __syncthreads();

        float* Sa = smem + (ch & 1) * STAGE_F;
        float* Sb = Sa + 4608;
        #pragma unroll
        for (int kk = 0; kk < 32; kk += 8) {
            unsigned af[2][4];
            #pragma unroll
            for (int mt = 0; mt < 2; mt++) {
                int m = wm * 32 + mt * 16 + g;
                af[mt][0] = f2tf(Sa[m * 36 + kk + tg]);
                af[mt][1] = f2tf(Sa[(m + 8) * 36 + kk + tg]);
                af[mt][2] = f2tf(Sa[m * 36 + kk + tg + 4]);
                af[mt][3] = f2tf(Sa[(m + 8) * 36 + kk + tg + 4]);
            }
            unsigned bf[8][2];
            #pragma unroll
            for (int nt = 0; nt < 8; nt++) {
                int n = wn * 64 + nt * 8 + g;
                if (BT) {
                    bf[nt][0] = f2tf(Sb[n * 36 + kk + tg]);
                    bf[nt][1] = f2tf(Sb[n * 36 + kk + tg + 4]);
                } else {
                    bf[nt][0] = f2tf(Sb[(kk + tg) * 132 + n]);
                    bf[nt][1] = f2tf(Sb[(kk + tg + 4) * 132 + n]);
                }
            }
            #pragma unroll
            for (int mt = 0; mt < 2; mt++)
                #pragma unroll
                for (int nt = 0; nt < 8; nt++)
                    mma8(acc[mt][nt], af[mt], bf[nt]);
        }
        __syncthreads();
    }

    // epilogue
    #pragma unroll
    for (int mt = 0; mt < 2; mt++) {
        int r0 = m0 + wm * 32 + mt * 16 + g;
        #pragma unroll
        for (int nt = 0; nt < 8; nt++) {
            int c = n0 + wn * 64 + nt * 8 + tg * 2;
            float b0 = bias ? bias[c] : 0.f, b1 = bias ? bias[c + 1] : 0.f;
            float2 v0, v1;
            v0.x = apply_act(acc[mt][nt][0] + b0, act);
            v0.y = apply_act(acc[mt][nt][1] + b1, act);
            v1.x = apply_act(acc[mt][nt][2] + b0, act);
            v1.y = apply_act(acc[mt][nt][3] + b1, act);
            *reinterpret_cast<float2*>(C + (size_t)r0 * ldc + c) = v0;
            *reinterpret_cast<float2*>(C + (size_t)(r0 + 8) * ldc + c) = v1;
        }
    }
}

// ---------------- fused attention scores as a virtual K=512 pipelined GEMM ----------------
// s[i,j] = (sum_k Q[i,k]K[j,k]  +  sum_k er[k,i]Q[j,k]) / 32
// chunks 0..7: A=Q rows i0 (NT layout), B=K rows j0
// chunks 8..15: A=er chunk [k][i] (NN layout), B=Q rows j0
__global__ void __launch_bounds__(256, 2)
scores_kernel(const float* __restrict__ q, const float* __restrict__ kx,
              const float* __restrict__ er, float* __restrict__ s)
{
    extern __shared__ float smem[];

    int bh = blockIdx.z;
    int b = bh >> 2, h = bh & 3;
    const float* qb = q  + (size_t)b * W_ * BINS_ + h * DH_;
    const float* kb = kx + (size_t)b * W_ * BINS_ + h * DH_;
    float* sb = s + (size_t)bh * W_ * W_;

    int i0 = blockIdx.y * 128, j0 = blockIdx.x * 128;
    int tid  = threadIdx.x;
    int lane = tid & 31, wid = tid >> 5;
    int g = lane >> 2, tg = lane & 3;
    int wm = wid & 3, wn = wid >> 2;

    float acc[2][8][4] = {};

    auto issue = [&](int t, int st) {
        float* Sa = smem + st * STAGE_F;
        float* Sb = Sa + 4608;
        int k0 = (t & 7) << 5;
        #pragma unroll
        for (int i = 0; i < 4; i++) {
            int idx = tid + i * 256;
            int r = idx >> 3, c = (idx & 7) << 2;
            if (t < 8) {
                cp16(Sa + r * 36 + c, qb + (size_t)(i0 + r) * BINS_ + k0 + c);
                cp16(Sb + r * 36 + c, kb + (size_t)(j0 + r) * BINS_ + k0 + c);
            } else {
                int kr = idx >> 5, cn = (idx & 31) << 2;
                cp16(Sa + kr * 132 + cn, er + (size_t)(k0 + kr) * W_ + i0 + cn);
                cp16(Sb + r * 36 + c, qb + (size_t)(j0 + r) * BINS_ + k0 + c);
            }
        }
        cp_commit();
    };

    issue(0, 0);
    for (int t = 0; t < 16; t++) {
        if (t + 1 < 16) { issue(t + 1, (t + 1) & 1); cp_wait1(); }
        else            { cp_wait0(); }
        __syncthreads();

        float* Sa = smem + (t & 1) * STAGE_F;
        float* Sb = Sa + 4608;
        bool nnA = (t >= 8);
        #pragma unroll
        for (int kk = 0; kk < 32; kk += 8) {
            unsigned af[2][4];
            #pragma unroll
            for (int mt = 0; mt < 2; mt++) {
                int m = wm * 32 + mt * 16 + g;
                if (!nnA) {
                    af[mt][0] = f2tf(Sa[m * 36 + kk + tg]);
                    af[mt][1] = f2tf(Sa[(m + 8) * 36 + kk + tg]);
                    af[mt][2] = f2tf(Sa[m * 36 + kk + tg + 4]);
                    af[mt][3] = f2tf(Sa[(m + 8) * 36 + kk + tg + 4]);
                } else {
                    af[mt][0] = f2tf(Sa[(kk + tg) * 132 + m]);
                    af[mt][1] = f2tf(Sa[(kk + tg) * 132 + m + 8]);
                    af[mt][2] = f2tf(Sa[(kk + tg + 4) * 132 + m]);
                    af[mt][3] = f2tf(Sa[(kk + tg + 4) * 132 + m + 8]);
                }
            }
            unsigned bf[8][2];
            #pragma unroll
            for (int nt = 0; nt < 8; nt++) {
                int n = wn * 64 + nt * 8 + g;
                bf[nt][0] = f2tf(Sb[n * 36 + kk + tg]);
                bf[nt][1] = f2tf(Sb[n * 36 + kk + tg + 4]);
            }
            #pragma unroll
            for (int mt = 0; mt < 2; mt++)
                #pragma unroll
                for (int nt = 0; nt < 8; nt++)
                    mma8(acc[mt][nt], af[mt], bf[nt]);
        }
        __syncthreads();
    }

    #pragma unroll
    for (int mt = 0; mt < 2; mt++) {
        int r0 = i0 + wm * 32 + mt * 16 + g;
        #pragma unroll
        for (int nt = 0; nt < 8; nt++) {
            int c = j0 + wn * 64 + nt * 8 + tg * 2;
            float2 v0, v1;
            v0.x = acc[mt][nt][0] * 0.03125f;
            v0.y = acc[mt][nt][1] * 0.03125f;
            v1.x = acc[mt][nt][2] * 0.03125f;
            v1.y = acc[mt][nt][3] * 0.03125f;
            *reinterpret_cast<float2*>(sb + (size_t)r0 * W_ + c) = v0;
            *reinterpret_cast<float2*>(sb + (size_t)(r0 + 8) * W_ + c) = v1;
        }
    }
}

// ---------------- row softmax over n=1024 ----------------
__global__ void softmax_kernel(float* __restrict__ s)
{
    const int n = W_;
    float* row = s + (size_t)blockIdx.x * n;
    int tid = threadIdx.x;
    __shared__ float red[8];

    float m = -3.4e38f;
    for (int i = tid; i < n; i += 256) m = fmaxf(m, row[i]);
    #pragma unroll
    for (int o = 16; o; o >>= 1) m = fmaxf(m, __shfl_xor_sync(0xffffffffu, m, o));
    if ((tid & 31) == 0) red[tid >> 5] = m;
    __syncthreads();
    m = red[0];
    #pragma unroll
    for (int wi = 1; wi < 8; wi++) m = fmaxf(m, red[wi]);

    float sum = 0.f;
    for (int i = tid; i < n; i += 256) { float e = __expf(row[i] - m); row[i] = e; sum += e; }
    #pragma unroll
    for (int o = 16; o; o >>= 1) sum += __shfl_xor_sync(0xffffffffu, sum, o);
    __syncthreads();
    if ((tid & 31) == 0) red[tid >> 5] = sum;
    __syncthreads();
    float tot = 0.f;
    #pragma unroll
    for (int wi = 0; wi < 8; wi++) tot += red[wi];
    float inv = 1.f / tot;
    for (int i = tid; i < n; i += 256) row[i] *= inv;
}

// ---------------- fused (a*omega + b + c) -> LayerNorm ----------------
__global__ void ln_kernel(const float* __restrict__ a, const float* __restrict__ bsrc,
                          const float* __restrict__ csrc, const float* __restrict__ omega,
                          const float* __restrict__ g, const float* __restrict__ bet,
                          float* __restrict__ out, int R)
{
    extern __shared__ float sm[];
    __shared__ float rs[8], rq[8];
    size_t base = (size_t)blockIdx.x * R;
    int tid = threadIdx.x;

    float s = 0.f, sq = 0.f;
    for (int i = tid; i < R; i += 256) {
        float v = a[base + i];
        if (omega) v *= omega[i];
        if (bsrc)  v += bsrc[base + i];
        if (csrc)  v += csrc[base + i];
        sm[i] = v; s += v; sq += v * v;
    }
    #pragma unroll
    for (int o = 16; o; o >>= 1) {
        s  += __shfl_xor_sync(0xffffffffu, s, o);
        sq += __shfl_xor_sync(0xffffffffu, sq, o);
    }
    if ((tid & 31) == 0) { rs[tid >> 5] = s; rq[tid >> 5] = sq; }
    __syncthreads();
    float ts = 0.f, tq = 0.f;
    #pragma unroll
    for (int wi = 0; wi < 8; wi++) { ts += rs[wi]; tq += rq[wi]; }
    float mean = ts / (float)R;
    float var  = tq / (float)R - mean * mean;
    float inv  = rsqrtf(var + 1e-5f);
    for (int i = tid; i < R; i += 256)
        out[base + i] = (sm[i] - mean) * inv * g[i] + bet[i];
}

// ---------------- depthwise conv along w, layout [B, W, Ch] ----------------
__global__ void dwconv_kernel(const float* __restrict__ in, const float* __restrict__ wk,
                              float* __restrict__ out, int Ch, int Kt, int pad)
{
    int c = blockIdx.x * blockDim.x + threadIdx.x;
    int w = blockIdx.y, b = blockIdx.z;
    const float* ib = in + ((size_t)b * W_) * Ch;
    float acc = 0.f;
    for (int t = 0; t < Kt; t++) {
        int ww = w + t - pad;
        if (ww >= 0 && ww < W_) acc += ib[(size_t)ww * Ch + c] * wk[c * Kt + t];
    }
    out[((size_t)b * W_ + w) * Ch + c] = acc;
}

// ---------------- hL[:, :FFH] += hR ----------------
__global__ void add_pad_kernel(float* __restrict__ ffa, const float* __restrict__ ffb)
{
    size_t idx = (size_t)blockIdx.x * 256 + threadIdx.x;   // over B*W*FFH
    size_t row = idx / FFH_, f = idx % FFH_;
    ffa[row * FF2_ + f] += ffb[idx];
}

// =========================================================================
static void launch_tgemm(const float* A, int lda, long soA, long siA,
                         const float* Bp, int ldb, long soB, long siB,
                         const float* bias, float* C, int ldc, long soC, long siC,
                         int M, int N, int K, int nz, int zdiv, int BT, int act)
{
    dim3 g(N / 128, M / 128, nz);
    if (BT)
        tgemm_kernel<1><<<g, 256, SMEM_BYTES>>>(A, lda, soA, siA, Bp, ldb, soB, siB, bias,
                                                C, ldc, soC, siC, K, zdiv, act);
    else
        tgemm_kernel<0><<<g, 256, SMEM_BYTES>>>(A, lda, soA, siA, Bp, ldb, soB, siB, bias,
                                                C, ldc, soC, siC, K, zdiv, act);
}

static void run_attn(const float* xin, const float* min_,
                     const float* w, const float* bias, const float* er,
                     float* q, float* k, float* v, float* att, float* scores,
                     float* outp)
{
    const long NK = (long)BINS_ * BINS_;
    const int M = B_ * W_;
    launch_tgemm(xin,  BINS_, 0, 0, w + 0 * NK, BINS_, 0, 0, bias + 0 * BINS_, q,   BINS_, 0, 0, M, BINS_, BINS_, 1, 1, 1, 0);
    launch_tgemm(min_, BINS_, 0, 0, w + 1 * NK, BINS_, 0, 0, bias + 1 * BINS_, k,   BINS_, 0, 0, M, BINS_, BINS_, 1, 1, 1, 0);
    launch_tgemm(min_, BINS_, 0, 0, w + 2 * NK, BINS_, 0, 0, bias + 2 * BINS_, v,   BINS_, 0, 0, M, BINS_, BINS_, 1, 1, 1, 0);

    dim3 gs(W_ / 128, W_ / 128, B_ * H_);
    scores_kernel<<<gs, 256, SMEM_BYTES>>>(q, k, er, scores);
    softmax_kernel<<<B_ * H_ * W_, 256>>>(scores);

    // att[b, i, h*DH+d] = sum_j scores[b,h,i,j] * v[b, j, h*DH+d]   (batched NN)
    launch_tgemm(scores, W_, 4L * W_ * W_, (long)W_ * W_,
                 v, BINS_, (long)W_ * BINS_, DH_,
                 nullptr,
                 att, BINS_, (long)W_ * BINS_, DH_,
                 W_, DH_, W_, B_ * H_, H_, 0, 0);

    launch_tgemm(att, BINS_, 0, 0, w + 3 * NK, BINS_, 0, 0, bias + 3 * BINS_, outp, BINS_, 0, 0, M, BINS_, BINS_, 1, 1, 1, 0);
}

extern "C" void kernel_launch(void* const* d_in, const int* in_sizes, int n_in,
                              void* d_out, int out_size)
{
    (void)in_sizes; (void)n_in; (void)out_size;

    cudaFuncSetAttribute(tgemm_kernel<0>, cudaFuncAttributeMaxDynamicSharedMemorySize, SMEM_BYTES);
    cudaFuncSetAttribute(tgemm_kernel<1>, cudaFuncAttributeMaxDynamicSharedMemorySize, SMEM_BYTES);
    cudaFuncSetAttribute(scores_kernel,   cudaFuncAttributeMaxDynamicSharedMemorySize, SMEM_BYTES);

    const float* x      = (const float*)d_in[0];
    const float* mem    = (const float*)d_in[1];
    const float* in_w   = (const float*)d_in[2];
    const float* skip_w = (const float*)d_in[3];
    const float* attn_w = (const float*)d_in[4];
    const float* attn_b = (const float*)d_in[5];
    const float* er     = (const float*)d_in[6];
    const float* omega  = (const float*)d_in[7];
    const float* ln_g   = (const float*)d_in[8];
    const float* ln_b   = (const float*)d_in[9];
    const float* ln2_g  = (const float*)d_in[10];
    const float* ln2_b  = (const float*)d_in[11];
    const float* c1L_dw = (const float*)d_in[12];
    const float* c1L_pw = (const float*)d_in[13];
    const float* c1R_dw = (const float*)d_in[14];
    const float* c1R_pw = (const float*)d_in[15];
    const float* c2_dw  = (const float*)d_in[16];
    const float* c2_pw  = (const float*)d_in[17];
    const float* c3_w   = (const float*)d_in[18];
    const float* c4_w   = (const float*)d_in[19];

    float *p_xs, *p_ms, *p_q, *p_k, *p_v, *p_att, *p_hs, *p_hm, *p_t1, *p_t2;
    float *p_dwc, *p_ffb, *p_scores, *p_ffa, *p_dwf;
    cudaGetSymbolAddress((void**)&p_xs,  g_xs);
    cudaGetSymbolAddress((void**)&p_ms,  g_ms);
    cudaGetSymbolAddress((void**)&p_q,   g_q);
    cudaGetSymbolAddress((void**)&p_k,   g_k);
    cudaGetSymbolAddress((void**)&p_v,   g_v);
    cudaGetSymbolAddress((void**)&p_att, g_att);
    cudaGetSymbolAddress((void**)&p_hs,  g_hs);
    cudaGetSymbolAddress((void**)&p_hm,  g_hm);
    cudaGetSymbolAddress((void**)&p_t1,  g_t1);
    cudaGetSymbolAddress((void**)&p_t2,  g_t2);
    cudaGetSymbolAddress((void**)&p_dwc, g_dwc);
    cudaGetSymbolAddress((void**)&p_ffb, g_ffb);
    cudaGetSymbolAddress((void**)&p_scores, g_scores);
    cudaGetSymbolAddress((void**)&p_ffa, g_ffa);
    cudaGetSymbolAddress((void**)&p_dwf, g_dwf);

    const int  M  = B_ * W_;
    const long ANK = 4L * BINS_ * BINS_;   // per-attention weight stride
    const long ERS = (long)DH_ * W_;

    // input / skip projections
    {
        dim3 g(W_ / 32, BINS_ / 32, B_), blk(32, 8);
        project_kernel<<<g, blk>>>(x,   in_w,   8, p_xs);
        project_kernel<<<g, blk>>>(mem, skip_w, 8, p_ms);
    }

    // self_attn1 / enc_attn1
    run_attn(p_xs, p_xs, attn_w + 0 * ANK, attn_b + 0 * 4 * BINS_, er + 0 * ERS,
             p_q, p_k, p_v, p_att, p_scores, p_hs);
    run_attn(p_xs, p_ms, attn_w + 1 * ANK, attn_b + 1 * 4 * BINS_, er + 1 * ERS,
             p_q, p_k, p_v, p_att, p_scores, p_hm);

    // x1 = LN(xs*omega0 + hs + hm)
    ln_kernel<<<M, 256, BINS_ * 4>>>(p_xs, p_hs, p_hm, omega + 0 * BINS_,
                                     ln_g + 0 * BINS_, ln_b + 0 * BINS_, p_t1, BINS_);

    // conv block
    dwconv_kernel<<<dim3(BINS_ / 256, W_, B_), 256>>>(p_t1, c1L_dw, p_dwc, BINS_, 11, 5);
    launch_tgemm(p_dwc, BINS_, 0, 0, c1L_pw, BINS_, 0, 0, nullptr, p_ffa, FF2_, 0, 0,
                 M, FF2_, BINS_, 1, 1, 1, 1 /*lrelu*/);
    dwconv_kernel<<<dim3(BINS_ / 256, W_, B_), 256>>>(p_t1, c1R_dw, p_dwc, BINS_, 7, 3);
    launch_tgemm(p_dwc, BINS_, 0, 0, c1R_pw, BINS_, 0, 0, nullptr, p_ffb, FFH_, 0, 0,
                 M, FFH_, BINS_, 1, 1, 1, 0);
    add_pad_kernel<<<(B_ * W_ * FFH_) / 256, 256>>>(p_ffa, p_ffb);
    ln_kernel<<<M, 256, FF2_ * 4>>>(p_ffa, nullptr, nullptr, nullptr, ln2_g, ln2_b, p_ffa, FF2_);
    dwconv_kernel<<<dim3(FF2_ / 256, W_, B_), 256>>>(p_ffa, c2_dw, p_dwf, FF2_, 7, 3);
    launch_tgemm(p_dwf, FF2_, 0, 0, c2_pw, FF2_, 0, 0, nullptr, p_hs, BINS_, 0, 0,
                 M, BINS_, FF2_, 1, 1, 1, 0);

    // x2 = LN(x1*omega1 + h)
    ln_kernel<<<M, 256, BINS_ * 4>>>(p_t1, p_hs, nullptr, omega + 1 * BINS_,
                                     ln_g + 1 * BINS_, ln_b + 1 * BINS_, p_t2, BINS_);

    // self_attn2 ; x3 = LN(x2*omega2 + h)
    run_attn(p_t2, p_t2, attn_w + 2 * ANK, attn_b + 2 * 4 * BINS_, er + 2 * ERS,
             p_q, p_k, p_v, p_att, p_scores, p_hs);
    ln_kernel<<<M, 256, BINS_ * 4>>>(p_t2, p_hs, nullptr, omega + 2 * BINS_,
                                     ln_g + 2 * BINS_, ln_b + 2 * BINS_, p_t1, BINS_);

    // enc_attn2 ; x4 = LN(x3*omega3 + h)
    run_attn(p_t1, p_ms, attn_w + 3 * ANK, attn_b + 3 * 4 * BINS_, er + 3 * ERS,
             p_q, p_k, p_v, p_att, p_scores, p_hs);
    ln_kernel<<<M, 256, BINS_ * 4>>>(p_t1, p_hs, nullptr, omega + 3 * BINS_,
                                     ln_g + 3 * BINS_, ln_b + 3 * BINS_, p_t2, BINS_);

    // FFN: silu(x4 @ c3^T) @ c4^T
    launch_tgemm(p_t2, BINS_, 0, 0, c3_w, BINS_, 0, 0, nullptr, p_ffa, FF2_, 0, 0,
                 M, FF2_, BINS_, 1, 1, 1, 2 /*silu*/);
    launch_tgemm(p_ffa, FF2_, 0, 0, c4_w, FF2_, 0, 0, nullptr, p_hs, BINS_, 0, 0,
                 M, BINS_, FF2_, 1, 1, 1, 0);

    // out = LN(x4*omega4 + h), then transpose to [B, BINS, W]
    ln_kernel<<<M, 256, BINS_ * 4>>>(p_t2, p_hs, nullptr, omega + 4 * BINS_,
                                     ln_g + 4 * BINS_, ln_b + 4 * BINS_, p_t1, BINS_);
    {
        dim3 g(W_ / 32, BINS_ / 32, B_), blk(32, 8);
        transpose_out_kernel<<<g, blk>>>(p_t1, (float*)d_out);
    }
}

// round 5
// speedup vs baseline: 3.0359x; 1.0669x over previous
#include <cuda_runtime.h>
#include <math.h>

#define B_    4
#define W_    1024
#define BINS_ 1024
#define H_    4
#define DH_   256
#define FF2_  4096
#define FFH_  1024

// stage layout for pipelined GEMMs: A(4608 floats) + B(4608 floats) per stage, 2 stages
#define STAGE_F 9216
#define SMEM_BYTES (2 * STAGE_F * 4)

// ---------------- scratch (static device memory; no allocations) ----------------
__device__ float g_xs [(size_t)B_*W_*BINS_];
__device__ float g_ms [(size_t)B_*W_*BINS_];
__device__ float g_q  [(size_t)B_*W_*BINS_];
__device__ float g_k  [(size_t)B_*W_*BINS_];
__device__ float g_v  [(size_t)B_*W_*BINS_];
__device__ float g_att[(size_t)B_*W_*BINS_];
__device__ float g_hs [(size_t)B_*W_*BINS_];
__device__ float g_hm [(size_t)B_*W_*BINS_];
__device__ float g_t1 [(size_t)B_*W_*BINS_];
__device__ float g_t2 [(size_t)B_*W_*BINS_];
__device__ float g_dwc[(size_t)B_*W_*BINS_];
__device__ float g_ffb[(size_t)B_*W_*FFH_];
__device__ float g_scores[(size_t)B_*H_*W_*W_];
__device__ float g_ffa[(size_t)B_*W_*FF2_];
__device__ float g_dwf[(size_t)B_*W_*FF2_];

// rounded weights: attn_w | er | c1L_pw | c1R_pw | c2_pw | c3_w | c4_w
#define OFF_AW   0L
#define OFF_ER   16777216L
#define OFF_C1L  17825792L
#define OFF_C1R  22020096L
#define OFF_C2   23068672L
#define OFF_C3   27262976L
#define OFF_C4   31457280L
#define WR_TOTAL 35651584L
__device__ float g_wr[WR_TOTAL];

// ---------------- helpers ----------------
__device__ __forceinline__ unsigned f2tf(float f) {
    unsigned r;
    asm("cvt.rna.tf32.f32 %0, %1;" : "=r"(r) : "f"(f));
    return r;
}
__device__ __forceinline__ float tfr(float f) { return __uint_as_float(f2tf(f)); }

__device__ __forceinline__ void mma8(float* d, const unsigned* a, const unsigned* b) {
    asm("mma.sync.aligned.m16n8k8.row.col.f32.tf32.tf32.f32 "
        "{%0,%1,%2,%3},{%4,%5,%6,%7},{%8,%9},{%0,%1,%2,%3};"
        : "+f"(d[0]), "+f"(d[1]), "+f"(d[2]), "+f"(d[3])
        : "r"(a[0]), "r"(a[1]), "r"(a[2]), "r"(a[3]), "r"(b[0]), "r"(b[1]));
}

__device__ __forceinline__ void cp16(float* smem_dst, const float* gsrc) {
    unsigned d = (unsigned)__cvta_generic_to_shared(smem_dst);
    asm volatile("cp.async.cg.shared.global [%0], [%1], 16;" :: "r"(d), "l"(gsrc));
}
__device__ __forceinline__ void cp_commit() { asm volatile("cp.async.commit_group;"); }
__device__ __forceinline__ void cp_wait1()  { asm volatile("cp.async.wait_group 1;"); }
__device__ __forceinline__ void cp_wait0()  { asm volatile("cp.async.wait_group 0;"); }

__device__ __forceinline__ float apply_act(float v, int act) {
    if (act == 1) return (v >= 0.f) ? v : 0.01f * v;
    if (act == 2) return v / (1.f + __expf(-v));
    return v;
}

// ---------------- tf32 rounding copy (weights) ----------------
__global__ void round_kernel(const float4* __restrict__ in, float4* __restrict__ out, int n4)
{
    int i = blockIdx.x * 256 + threadIdx.x;
    if (i < n4) {
        float4 v = in[i];
        v.x = tfr(v.x); v.y = tfr(v.y); v.z = tfr(v.z); v.w = tfr(v.w);
        out[i] = v;
    }
}

// ---------------- input projection: out[b,w,h] = sum_c x[b,c,h,w] * wc[c] ----------------
__global__ void project_kernel(const float* __restrict__ x, const float* __restrict__ wc,
                               int Cn, float* __restrict__ out)
{
    __shared__ float tile[32][33];
    int b  = blockIdx.z;
    int h0 = blockIdx.y * 32, w0 = blockIdx.x * 32;
    int tx = threadIdx.x, ty = threadIdx.y;   // 32 x 8

    float wreg[8];
    #pragma unroll
    for (int c = 0; c < 8; c++) wreg[c] = (c < Cn) ? wc[c] : 0.f;

    #pragma unroll
    for (int r = 0; r < 4; r++) {
        int h = h0 + ty + r * 8;
        float acc = 0.f;
        #pragma unroll
        for (int c = 0; c < 8; c++)
            acc += x[(((size_t)b * Cn + c) * BINS_ + h) * W_ + (w0 + tx)] * wreg[c];
        tile[ty + r * 8][tx] = tfr(acc);
    }
    __syncthreads();
    #pragma unroll
    for (int r = 0; r < 4; r++) {
        int w = w0 + ty + r * 8;
        out[((size_t)b * W_ + w) * BINS_ + (h0 + tx)] = tile[tx][ty + r * 8];
    }
}

// ---------------- final transpose: out[b,h,w] = in[b,w,h] ----------------
__global__ void transpose_out_kernel(const float* __restrict__ in, float* __restrict__ out)
{
    __shared__ float tile[32][33];
    int b  = blockIdx.z;
    int w0 = blockIdx.x * 32, h0 = blockIdx.y * 32;
    int tx = threadIdx.x, ty = threadIdx.y;

    #pragma unroll
    for (int r = 0; r < 4; r++)
        tile[ty + r * 8][tx] = in[((size_t)b * W_ + (w0 + ty + r * 8)) * BINS_ + (h0 + tx)];
    __syncthreads();
    #pragma unroll
    for (int r = 0; r < 4; r++)
        out[((size_t)b * BINS_ + (h0 + ty + r * 8)) * W_ + (w0 + tx)] = tile[tx][ty + r * 8];
}

// ---------------- tf32 tensor-core GEMM, cp.async double-buffered ----------------
// All operands MUST be pre-rounded to tf32 representable values (no cvt inside).
// BT=1: B is [N,K] row-major (NT); BT=0: B is [K,N] row-major (NN)
// rnd=1: round output to tf32 (for outputs feeding another GEMM directly)
template <int BT>
__global__ void __launch_bounds__(256, 2)
tgemm_kernel(const float* __restrict__ A, int lda, long soA, long siA,
             const float* __restrict__ Bp, int ldb, long soB, long siB,
             const float* __restrict__ bias,
             float* __restrict__ C, int ldc, long soC, long siC,
             int K, int zdiv, int act, int rnd)
{
    extern __shared__ float smem[];

    int z = blockIdx.z;
    long zo = z / zdiv, zi = z % zdiv;
    A  += zo * soA + zi * siA;
    Bp += zo * soB + zi * siB;
    C  += zo * soC + zi * siC;

    int m0 = blockIdx.y * 128, n0 = blockIdx.x * 128;
    int tid  = threadIdx.x;
    int lane = tid & 31, wid = tid >> 5;
    int g = lane >> 2, tg = lane & 3;
    int wm = wid & 3, wn = wid >> 2;      // warp grid 4 (m) x 2 (n)

    float acc[2][8][4] = {};

    auto issue = [&](int k0, int s) {
        float* Sa = smem + s * STAGE_F;
        float* Sb = Sa + 4608;
        #pragma unroll
        for (int i = 0; i < 4; i++) {
            int idx = tid + i * 256;
            int r = idx >> 3, c = (idx & 7) << 2;
            cp16(Sa + r * 36 + c, A + (size_t)(m0 + r) * lda + k0 + c);
            if (BT) {
                cp16(Sb + r * 36 + c, Bp + (size_t)(n0 + r) * ldb + k0 + c);
            } else {
                int kr = idx >> 5, cn = (idx & 31) << 2;
                cp16(Sb + kr * 132 + cn, Bp + (size_t)(k0 + kr) * ldb + n0 + cn);
            }
        }
        cp_commit();
    };

    int nc = K >> 5;
    issue(0, 0);
    for (int ch = 0; ch < nc; ch++) {
        if (ch + 1 < nc) { issue((ch + 1) << 5, (ch + 1) & 1); cp_wait1(); }
        else             { cp_wait0(); }
        __syncthreads();

        const unsigned* Ua = (const unsigned*)(smem + (ch & 1) * STAGE_F);
        const unsigned* Ub = Ua + 4608;
        #pragma unroll
        for (int kk = 0; kk < 32; kk += 8) {
            unsigned af[2][4];
            #pragma unroll
            for (int mt = 0; mt < 2; mt++) {
                int m = wm * 32 + mt * 16 + g;
                af[mt][0] = Ua[m * 36 + kk + tg];
                af[mt][1] = Ua[(m + 8) * 36 + kk + tg];
                af[mt][2] = Ua[m * 36 + kk + tg + 4];
                af[mt][3] = Ua[(m + 8) * 36 + kk + tg + 4];
            }
            unsigned bf[8][2];
            #pragma unroll
            for (int nt = 0; nt < 8; nt++) {
                int n = wn * 64 + nt * 8 + g;
                if (BT) {
                    bf[nt][0] = Ub[n * 36 + kk + tg];
                    bf[nt][1] = Ub[n * 36 + kk + tg + 4];
                } else {
                    bf[nt][0] = Ub[(kk + tg) * 132 + n];
                    bf[nt][1] = Ub[(kk + tg + 4) * 132 + n];
                }
            }
            #pragma unroll
            for (int mt = 0; mt < 2; mt++)
                #pragma unroll
                for (int nt = 0; nt < 8; nt++)
                    mma8(acc[mt][nt], af[mt], bf[nt]);
        }
        __syncthreads();
    }

    // epilogue
    #pragma unroll
    for (int mt = 0; mt < 2; mt++) {
        int r0 = m0 + wm * 32 + mt * 16 + g;
        #pragma unroll
        for (int nt = 0; nt < 8; nt++) {
            int c = n0 + wn * 64 + nt * 8 + tg * 2;
            float b0 = bias ? bias[c] : 0.f, b1 = bias ? bias[c + 1] : 0.f;
            float vv[4];
            vv[0] = apply_act(acc[mt][nt][0] + b0, act);
            vv[1] = apply_act(acc[mt][nt][1] + b1, act);
            vv[2] = apply_act(acc[mt][nt][2] + b0, act);
            vv[3] = apply_act(acc[mt][nt][3] + b1, act);
            if (rnd) {
                vv[0] = tfr(vv[0]); vv[1] = tfr(vv[1]);
                vv[2] = tfr(vv[2]); vv[3] = tfr(vv[3]);
            }
            *reinterpret_cast<float2*>(C + (size_t)r0 * ldc + c)       = make_float2(vv[0], vv[1]);
            *reinterpret_cast<float2*>(C + (size_t)(r0 + 8) * ldc + c) = make_float2(vv[2], vv[3]);
        }
    }
}

// ---------------- fused attention scores as a virtual K=512 pipelined GEMM ----------------
// s[i,j] = (sum_k Q[i,k]K[j,k]  +  sum_k er[k,i]Q[j,k]) / 32
// Operands pre-rounded to tf32. chunks 0..7: Q/K (NT); chunks 8..15: er (NN) / Q (NT)
__global__ void __launch_bounds__(256, 2)
scores_kernel(const float* __restrict__ q, const float* __restrict__ kx,
              const float* __restrict__ er, float* __restrict__ s)
{
    extern __shared__ float smem[];

    int bh = blockIdx.z;
    int b = bh >> 2, h = bh & 3;
    const float* qb = q  + (size_t)b * W_ * BINS_ + h * DH_;
    const float* kb = kx + (size_t)b * W_ * BINS_ + h * DH_;
    float* sb = s + (size_t)bh * W_ * W_;

    int i0 = blockIdx.y * 128, j0 = blockIdx.x * 128;
    int tid  = threadIdx.x;
    int lane = tid & 31, wid = tid >> 5;
    int g = lane >> 2, tg = lane & 3;
    int wm = wid & 3, wn = wid >> 2;

    float acc[2][8][4] = {};

    auto issue = [&](int t, int st) {
        float* Sa = smem + st * STAGE_F;
        float* Sb = Sa + 4608;
        int k0 = (t & 7) << 5;
        #pragma unroll
        for (int i = 0; i < 4; i++) {
            int idx = tid + i * 256;
            int r = idx >> 3, c = (idx & 7) << 2;
            if (t < 8) {
                cp16(Sa + r * 36 + c, qb + (size_t)(i0 + r) * BINS_ + k0 + c);
                cp16(Sb + r * 36 + c, kb + (size_t)(j0 + r) * BINS_ + k0 + c);
            } else {
                int kr = idx >> 5, cn = (idx & 31) << 2;
                cp16(Sa + kr * 132 + cn, er + (size_t)(k0 + kr) * W_ + i0 + cn);
                cp16(Sb + r * 36 + c, qb + (size_t)(j0 + r) * BINS_ + k0 + c);
            }
        }
        cp_commit();
    };

    issue(0, 0);
    for (int t = 0; t < 16; t++) {
        if (t + 1 < 16) { issue(t + 1, (t + 1) & 1); cp_wait1(); }
        else            { cp_wait0(); }
        __syncthreads();

        const unsigned* Ua = (const unsigned*)(smem + (t & 1) * STAGE_F);
        const unsigned* Ub = Ua + 4608;
        bool nnA = (t >= 8);
        #pragma unroll
        for (int kk = 0; kk < 32; kk += 8) {
            unsigned af[2][4];
            #pragma unroll
            for (int mt = 0; mt < 2; mt++) {
                int m = wm * 32 + mt * 16 + g;
                if (!nnA) {
                    af[mt][0] = Ua[m * 36 + kk + tg];
                    af[mt][1] = Ua[(m + 8) * 36 + kk + tg];
                    af[mt][2] = Ua[m * 36 + kk + tg + 4];
                    af[mt][3] = Ua[(m + 8) * 36 + kk + tg + 4];
                } else {
                    af[mt][0] = Ua[(kk + tg) * 132 + m];
                    af[mt][1] = Ua[(kk + tg) * 132 + m + 8];
                    af[mt][2] = Ua[(kk + tg + 4) * 132 + m];
                    af[mt][3] = Ua[(kk + tg + 4) * 132 + m + 8];
                }
            }
            unsigned bf[8][2];
            #pragma unroll
            for (int nt = 0; nt < 8; nt++) {
                int n = wn * 64 + nt * 8 + g;
                bf[nt][0] = Ub[n * 36 + kk + tg];
                bf[nt][1] = Ub[n * 36 + kk + tg + 4];
            }
            #pragma unroll
            for (int mt = 0; mt < 2; mt++)
                #pragma unroll
                for (int nt = 0; nt < 8; nt++)
                    mma8(acc[mt][nt], af[mt], bf[nt]);
        }
        __syncthreads();
    }

    #pragma unroll
    for (int mt = 0; mt < 2; mt++) {
        int r0 = i0 + wm * 32 + mt * 16 + g;
        #pragma unroll
        for (int nt = 0; nt < 8; nt++) {
            int c = j0 + wn * 64 + nt * 8 + tg * 2;
            float2 v0, v1;
            v0.x = acc[mt][nt][0] * 0.03125f;
            v0.y = acc[mt][nt][1] * 0.03125f;
            v1.x = acc[mt][nt][2] * 0.03125f;
            v1.y = acc[mt][nt][3] * 0.03125f;
            *reinterpret_cast<float2*>(sb + (size_t)r0 * W_ + c) = v0;
            *reinterpret_cast<float2*>(sb + (size_t)(r0 + 8) * W_ + c) = v1;
        }
    }
}

// ---------------- row softmax over n=1024 (output rounded to tf32) ----------------
__global__ void softmax_kernel(float* __restrict__ s)
{
    const int n = W_;
    float* row = s + (size_t)blockIdx.x * n;
    int tid = threadIdx.x;
    __shared__ float red[8];

    float m = -3.4e38f;
    for (int i = tid; i < n; i += 256) m = fmaxf(m, row[i]);
    #pragma unroll
    for (int o = 16; o; o >>= 1) m = fmaxf(m, __shfl_xor_sync(0xffffffffu, m, o));
    if ((tid & 31) == 0) red[tid >> 5] = m;
    __syncthreads();
    m = red[0];
    #pragma unroll
    for (int wi = 1; wi < 8; wi++) m = fmaxf(m, red[wi]);

    float sum = 0.f;
    for (int i = tid; i < n; i += 256) { float e = __expf(row[i] - m); row[i] = e; sum += e; }
    #pragma unroll
    for (int o = 16; o; o >>= 1) sum += __shfl_xor_sync(0xffffffffu, sum, o);
    __syncthreads();
    if ((tid & 31) == 0) red[tid >> 5] = sum;
    __syncthreads();
    float tot = 0.f;
    #pragma unroll
    for (int wi = 0; wi < 8; wi++) tot += red[wi];
    float inv = 1.f / tot;
    for (int i = tid; i < n; i += 256) row[i] = tfr(row[i] * inv);
}

// ---------------- fused (a*omega + b + c) -> LayerNorm ----------------
__global__ void ln_kernel(const float* __restrict__ a, const float* __restrict__ bsrc,
                          const float* __restrict__ csrc, const float* __restrict__ omega,
                          const float* __restrict__ g, const float* __restrict__ bet,
                          float* __restrict__ out, int R, int rnd)
{
    extern __shared__ float sm[];
    __shared__ float rs[8], rq[8];
    size_t base = (size_t)blockIdx.x * R;
    int tid = threadIdx.x;

    float s = 0.f, sq = 0.f;
    for (int i = tid; i < R; i += 256) {
        float v = a[base + i];
        if (omega) v *= omega[i];
        if (bsrc)  v += bsrc[base + i];
        if (csrc)  v += csrc[base + i];
        sm[i] = v; s += v; sq += v * v;
    }
    #pragma unroll
    for (int o = 16; o; o >>= 1) {
        s  += __shfl_xor_sync(0xffffffffu, s, o);
        sq += __shfl_xor_sync(0xffffffffu, sq, o);
    }
    if ((tid & 31) == 0) { rs[tid >> 5] = s; rq[tid >> 5] = sq; }
    __syncthreads();
    float ts = 0.f, tq = 0.f;
    #pragma unroll
    for (int wi = 0; wi < 8; wi++) { ts += rs[wi]; tq += rq[wi]; }
    float mean = ts / (float)R;
    float var  = tq / (float)R - mean * mean;
    float inv  = rsqrtf(var + 1e-5f);
    for (int i = tid; i < R; i += 256) {
        float v = (sm[i] - mean) * inv * g[i] + bet[i];
        out[base + i] = rnd ? tfr(v) : v;
    }
}

// ---------------- depthwise conv along w, layout [B, W, Ch] (output rounded) ----------------
__global__ void dwconv_kernel(const float* __restrict__ in, const float* __restrict__ wk,
                              float* __restrict__ out, int Ch, int Kt, int pad)
{
    int c = blockIdx.x * blockDim.x + threadIdx.x;
    int w = blockIdx.y, b = blockIdx.z;
    const float* ib = in + ((size_t)b * W_) * Ch;
    float acc = 0.f;
    for (int t = 0; t < Kt; t++) {
        int ww = w + t - pad;
        if (ww >= 0 && ww < W_) acc += ib[(size_t)ww * Ch + c] * wk[c * Kt + t];
    }
    out[((size_t)b * W_ + w) * Ch + c] = tfr(acc);
}

// ---------------- hL[:, :FFH] += hR ----------------
__global__ void add_pad_kernel(float* __restrict__ ffa, const float* __restrict__ ffb)
{
    size_t idx = (size_t)blockIdx.x * 256 + threadIdx.x;   // over B*W*FFH
    size_t row = idx / FFH_, f = idx % FFH_;
    ffa[row * FF2_ + f] += ffb[idx];
}

// =========================================================================
static void launch_tgemm(const float* A, int lda, long soA, long siA,
                         const float* Bp, int ldb, long soB, long siB,
                         const float* bias, float* C, int ldc, long soC, long siC,
                         int M, int N, int K, int nz, int zdiv, int BT, int act, int rnd)
{
    dim3 g(N / 128, M / 128, nz);
    if (BT)
        tgemm_kernel<1><<<g, 256, SMEM_BYTES>>>(A, lda, soA, siA, Bp, ldb, soB, siB, bias,
                                                C, ldc, soC, siC, K, zdiv, act, rnd);
    else
        tgemm_kernel<0><<<g, 256, SMEM_BYTES>>>(A, lda, soA, siA, Bp, ldb, soB, siB, bias,
                                                C, ldc, soC, siC, K, zdiv, act, rnd);
}

static void run_attn(const float* xin, const float* min_,
                     const float* w, const float* bias, const float* er,
                     float* q, float* k, float* v, float* att, float* scores,
                     float* outp)
{
    const long NK = (long)BINS_ * BINS_;
    const int M = B_ * W_;
    launch_tgemm(xin,  BINS_, 0, 0, w + 0 * NK, BINS_, 0, 0, bias + 0 * BINS_, q,   BINS_, 0, 0, M, BINS_, BINS_, 1, 1, 1, 0, 1);
    launch_tgemm(min_, BINS_, 0, 0, w + 1 * NK, BINS_, 0, 0, bias + 1 * BINS_, k,   BINS_, 0, 0, M, BINS_, BINS_, 1, 1, 1, 0, 1);
    launch_tgemm(min_, BINS_, 0, 0, w + 2 * NK, BINS_, 0, 0, bias + 2 * BINS_, v,   BINS_, 0, 0, M, BINS_, BINS_, 1, 1, 1, 0, 1);

    dim3 gs(W_ / 128, W_ / 128, B_ * H_);
    scores_kernel<<<gs, 256, SMEM_BYTES>>>(q, k, er, scores);
    softmax_kernel<<<B_ * H_ * W_, 256>>>(scores);

    // att[b, i, h*DH+d] = sum_j scores[b,h,i,j] * v[b, j, h*DH+d]   (batched NN)
    launch_tgemm(scores, W_, 4L * W_ * W_, (long)W_ * W_,
                 v, BINS_, (long)W_ * BINS_, DH_,
                 nullptr,
                 att, BINS_, (long)W_ * BINS_, DH_,
                 W_, DH_, W_, B_ * H_, H_, 0, 0, 1);

    launch_tgemm(att, BINS_, 0, 0, w + 3 * NK, BINS_, 0, 0, bias + 3 * BINS_, outp, BINS_, 0, 0, M, BINS_, BINS_, 1, 1, 1, 0, 0);
}

extern "C" void kernel_launch(void* const* d_in, const int* in_sizes, int n_in,
                              void* d_out, int out_size)
{
    (void)in_sizes; (void)n_in; (void)out_size;

    cudaFuncSetAttribute(tgemm_kernel<0>, cudaFuncAttributeMaxDynamicSharedMemorySize, SMEM_BYTES);
    cudaFuncSetAttribute(tgemm_kernel<1>, cudaFuncAttributeMaxDynamicSharedMemorySize, SMEM_BYTES);
    cudaFuncSetAttribute(scores_kernel,   cudaFuncAttributeMaxDynamicSharedMemorySize, SMEM_BYTES);

    const float* x      = (const float*)d_in[0];
    const float* mem    = (const float*)d_in[1];
    const float* in_w   = (const float*)d_in[2];
    const float* skip_w = (const float*)d_in[3];
    const float* attn_w = (const float*)d_in[4];
    const float* attn_b = (const float*)d_in[5];
    const float* er     = (const float*)d_in[6];
    const float* omega  = (const float*)d_in[7];
    const float* ln_g   = (const float*)d_in[8];
    const float* ln_b   = (const float*)d_in[9];
    const float* ln2_g  = (const float*)d_in[10];
    const float* ln2_b  = (const float*)d_in[11];
    const float* c1L_dw = (const float*)d_in[12];
    const float* c1L_pw = (const float*)d_in[13];
    const float* c1R_dw = (const float*)d_in[14];
    const float* c1R_pw = (const float*)d_in[15];
    const float* c2_dw  = (const float*)d_in[16];
    const float* c2_pw  = (const float*)d_in[17];
    const float* c3_w   = (const float*)d_in[18];
    const float* c4_w   = (const float*)d_in[19];

    float *p_xs, *p_ms, *p_q, *p_k, *p_v, *p_att, *p_hs, *p_hm, *p_t1, *p_t2;
    float *p_dwc, *p_ffb, *p_scores, *p_ffa, *p_dwf, *p_wr;
    cudaGetSymbolAddress((void**)&p_xs,  g_xs);
    cudaGetSymbolAddress((void**)&p_ms,  g_ms);
    cudaGetSymbolAddress((void**)&p_q,   g_q);
    cudaGetSymbolAddress((void**)&p_k,   g_k);
    cudaGetSymbolAddress((void**)&p_v,   g_v);
    cudaGetSymbolAddress((void**)&p_att, g_att);
    cudaGetSymbolAddress((void**)&p_hs,  g_hs);
    cudaGetSymbolAddress((void**)&p_hm,  g_hm);
    cudaGetSymbolAddress((void**)&p_t1,  g_t1);
    cudaGetSymbolAddress((void**)&p_t2,  g_t2);
    cudaGetSymbolAddress((void**)&p_dwc, g_dwc);
    cudaGetSymbolAddress((void**)&p_ffb, g_ffb);
    cudaGetSymbolAddress((void**)&p_scores, g_scores);
    cudaGetSymbolAddress((void**)&p_ffa, g_ffa);
    cudaGetSymbolAddress((void**)&p_dwf, g_dwf);
    cudaGetSymbolAddress((void**)&p_wr,  g_wr);

    // ---- round all GEMM weight operands to tf32 once ----
    auto round_to = [&](const float* src, long off, long n) {
        int n4 = (int)(n >> 2);
        round_kernel<<<(n4 + 255) / 256, 256>>>((const float4*)src, (float4*)(p_wr + off), n4);
    };
    round_to(attn_w, OFF_AW,  16777216L);
    round_to(er,     OFF_ER,  1048576L);
    round_to(c1L_pw, OFF_C1L, 4194304L);
    round_to(c1R_pw, OFF_C1R, 1048576L);
    round_to(c2_pw,  OFF_C2,  4194304L);
    round_to(c3_w,   OFF_C3,  4194304L);
    round_to(c4_w,   OFF_C4,  4194304L);

    const float* aw_r  = p_wr + OFF_AW;
    const float* er_r  = p_wr + OFF_ER;
    const float* c1L_r = p_wr + OFF_C1L;
    const float* c1R_r = p_wr + OFF_C1R;
    const float* c2_r  = p_wr + OFF_C2;
    const float* c3_r  = p_wr + OFF_C3;
    const float* c4_r  = p_wr + OFF_C4;

    const int  M  = B_ * W_;
    const long ANK = 4L * BINS_ * BINS_;   // per-attention weight stride
    const long ERS = (long)DH_ * W_;

    // input / skip projections
    {
        dim3 g(W_ / 32, BINS_ / 32, B_), blk(32, 8);
        project_kernel<<<g, blk>>>(x,   in_w,   8, p_xs);
        project_kernel<<<g, blk>>>(mem, skip_w, 8, p_ms);
    }

    // self_attn1 / enc_attn1
    run_attn(p_xs, p_xs, aw_r + 0 * ANK, attn_b + 0 * 4 * BINS_, er_r + 0 * ERS,
             p_q, p_k, p_v, p_att, p_scores, p_hs);
    run_attn(p_xs, p_ms, aw_r + 1 * ANK, attn_b + 1 * 4 * BINS_, er_r + 1 * ERS,
             p_q, p_k, p_v, p_att, p_scores, p_hm);

    // x1 = LN(xs*omega0 + hs + hm)   (feeds dwconv only -> no round)
    ln_kernel<<<M, 256, BINS_ * 4>>>(p_xs, p_hs, p_hm, omega + 0 * BINS_,
                                     ln_g + 0 * BINS_, ln_b + 0 * BINS_, p_t1, BINS_, 0);

    // conv block
    dwconv_kernel<<<dim3(BINS_ / 256, W_, B_), 256>>>(p_t1, c1L_dw, p_dwc, BINS_, 11, 5);
    launch_tgemm(p_dwc, BINS_, 0, 0, c1L_r, BINS_, 0, 0, nullptr, p_ffa, FF2_, 0, 0,
                 M, FF2_, BINS_, 1, 1, 1, 1 /*lrelu*/, 0);
    dwconv_kernel<<<dim3(BINS_ / 256, W_, B_), 256>>>(p_t1, c1R_dw, p_dwc, BINS_, 7, 3);
    launch_tgemm(p_dwc, BINS_, 0, 0, c1R_r, BINS_, 0, 0, nullptr, p_ffb, FFH_, 0, 0,
                 M, FFH_, BINS_, 1, 1, 1, 0, 0);
    add_pad_kernel<<<(B_ * W_ * FFH_) / 256, 256>>>(p_ffa, p_ffb);
    ln_kernel<<<M, 256, FF2_ * 4>>>(p_ffa, nullptr, nullptr, nullptr, ln2_g, ln2_b, p_ffa, FF2_, 0);
    dwconv_kernel<<<dim3(FF2_ / 256, W_, B_), 256>>>(p_ffa, c2_dw, p_dwf, FF2_, 7, 3);
    launch_tgemm(p_dwf, FF2_, 0, 0, c2_r, FF2_, 0, 0, nullptr, p_hs, BINS_, 0, 0,
                 M, BINS_, FF2_, 1, 1, 1, 0, 0);

    // x2 = LN(x1*omega1 + h)  (feeds self_attn2 GEMM A -> round)
    ln_kernel<<<M, 256, BINS_ * 4>>>(p_t1, p_hs, nullptr, omega + 1 * BINS_,
                                     ln_g + 1 * BINS_, ln_b + 1 * BINS_, p_t2, BINS_, 1);

    // self_attn2 ; x3 = LN(x2*omega2 + h)  (feeds enc_attn2 -> round)
    run_attn(p_t2, p_t2, aw_r + 2 * ANK, attn_b + 2 * 4 * BINS_, er_r + 2 * ERS,
             p_q, p_k, p_v, p_att, p_scores, p_hs);
    ln_kernel<<<M, 256, BINS_ * 4>>>(p_t2, p_hs, nullptr, omega + 2 * BINS_,
                                     ln_g + 2 * BINS_, ln_b + 2 * BINS_, p_t1, BINS_, 1);

    // enc_attn2 ; x4 = LN(x3*omega3 + h)  (feeds c3 GEMM -> round)
    run_attn(p_t1, p_ms, aw_r + 3 * ANK, attn_b + 3 * 4 * BINS_, er_r + 3 * ERS,
             p_q, p_k, p_v, p_att, p_scores, p_hs);
    ln_kernel<<<M, 256, BINS_ * 4>>>(p_t1, p_hs, nullptr, omega + 3 * BINS_,
                                     ln_g + 3 * BINS_, ln_b + 3 * BINS_, p_t2, BINS_, 1);

    // FFN: silu(x4 @ c3^T) @ c4^T   (silu output feeds c4 GEMM -> round)
    launch_tgemm(p_t2, BINS_, 0, 0, c3_r, BINS_, 0, 0, nullptr, p_ffa, FF2_, 0, 0,
                 M, FF2_, BINS_, 1, 1, 1, 2 /*silu*/, 1);
    launch_tgemm(p_ffa, FF2_, 0, 0, c4_r, FF2_, 0, 0, nullptr, p_hs, BINS_, 0, 0,
                 M, BINS_, FF2_, 1, 1, 1, 0, 0);

    // out = LN(x4*omega4 + h) (final output -> NO round), then transpose to [B, BINS, W]
    ln_kernel<<<M, 256, BINS_ * 4>>>(p_t2, p_hs, nullptr, omega + 4 * BINS_,
                                     ln_g + 4 * BINS_, ln_b + 4 * BINS_, p_t1, BINS_, 0);
    {
        dim3 g(W_ / 32, BINS_ / 32, B_), blk(32, 8);
        transpose_out_kernel<<<g, blk>>>(p_t1, (float*)d_out);
    }
}